// round 2
// baseline (speedup 1.0000x reference)
#include <cuda_runtime.h>

#define N_PAD   3000
#define N_REAL  2500
#define F_IN    1024
#define H1      256
#define OUTD    128
#define GATES_N 512   // 4 gates x 128
#define MAX_E   1048576

// Scratch (device globals — no allocation allowed)
__device__ float g_xh  [N_PAD * H1];       // relu(fc0(x_pad))           3.07 MB
__device__ float g_agg [N_PAD * H1];       // mean-aggregated neighbors  3.07 MB
__device__ float g_gate[N_PAD * GATES_N];  // pre-activation gates       6.14 MB
__device__ int   g_deg [3072];             // in-degree (padded for scan)
__device__ int   g_row [3073];             // CSR row starts (exclusive scan)
__device__ int   g_cur [N_PAD];            // scatter cursors
__device__ int   g_csr [MAX_E];            // CSR column (src) indices

// ---------------------------------------------------------------------------
__global__ void zero_kernel() {
    int i = blockIdx.x * blockDim.x + threadIdx.x;
    if (i < 3072)  g_deg[i] = 0;
    if (i < N_PAD) g_cur[i] = 0;
}

// ---------------------------------------------------------------------------
// GEMM1: xh[m,n] = relu( sum_k x[m,k] * w[n,k] + b[n] ),  m<2500, n<256
// TN gemm, 64x64x16 tile, 256 threads, 4x4 accum per thread.
__global__ void gemm1_kernel(const float* __restrict__ x,
                             const float* __restrict__ w,
                             const float* __restrict__ bias) {
    __shared__ float As[16][68];
    __shared__ float Bs[16][68];
    const int bm = blockIdx.y * 64;
    const int bn = blockIdx.x * 64;
    const int tid = threadIdx.x;
    const int lr = tid >> 2;         // 0..63 tile row
    const int lk = (tid & 3) * 4;    // 0,4,8,12 within k-slab
    const int tx = tid & 15, ty = tid >> 4;

    float acc[4][4];
#pragma unroll
    for (int i = 0; i < 4; i++)
#pragma unroll
        for (int j = 0; j < 4; j++) acc[i][j] = 0.f;

    for (int k0 = 0; k0 < F_IN; k0 += 16) {
        float4 av = make_float4(0.f, 0.f, 0.f, 0.f);
        int gm = bm + lr;
        if (gm < N_REAL)
            av = *(const float4*)(x + (size_t)gm * F_IN + k0 + lk);
        As[lk + 0][lr] = av.x; As[lk + 1][lr] = av.y;
        As[lk + 2][lr] = av.z; As[lk + 3][lr] = av.w;

        float4 bv = *(const float4*)(w + (size_t)(bn + lr) * F_IN + k0 + lk);
        Bs[lk + 0][lr] = bv.x; Bs[lk + 1][lr] = bv.y;
        Bs[lk + 2][lr] = bv.z; Bs[lk + 3][lr] = bv.w;
        __syncthreads();

#pragma unroll
        for (int kk = 0; kk < 16; kk++) {
            float4 a4 = *(const float4*)&As[kk][ty * 4];
            float4 b4 = *(const float4*)&Bs[kk][tx * 4];
            float a[4] = {a4.x, a4.y, a4.z, a4.w};
            float b[4] = {b4.x, b4.y, b4.z, b4.w};
#pragma unroll
            for (int i = 0; i < 4; i++)
#pragma unroll
                for (int j = 0; j < 4; j++)
                    acc[i][j] = fmaf(a[i], b[j], acc[i][j]);
        }
        __syncthreads();
    }

#pragma unroll
    for (int i = 0; i < 4; i++) {
        int m = bm + ty * 4 + i;
        if (m >= N_REAL) continue;
#pragma unroll
        for (int j = 0; j < 4; j++) {
            int n = bn + tx * 4 + j;
            float v = acc[i][j] + bias[n];
            g_xh[m * H1 + n] = v > 0.f ? v : 0.f;
        }
    }
}

// Rows 2500..2999 of x_pad are zero -> xh row = relu(fc0_b)
__global__ void pad_xh_kernel(const float* __restrict__ bias) {
    int i = blockIdx.x * blockDim.x + threadIdx.x;
    if (i >= (N_PAD - N_REAL) * H1) return;
    float v = bias[i & (H1 - 1)];
    g_xh[N_REAL * H1 + i] = v > 0.f ? v : 0.f;
}

// ---------------------------------------------------------------------------
// CSR build
__global__ void count_kernel(const int* __restrict__ ei, int E) {
    int e = blockIdx.x * blockDim.x + threadIdx.x;
    if (e >= E) return;
    atomicAdd(&g_deg[ei[E + e]], 1);
}

// Exclusive scan over 3072 degrees: single block of 1024 threads, 3 elems each.
__global__ void scan_kernel() {
    const int tid = threadIdx.x;
    const int lane = tid & 31, wid = tid >> 5;
    int base = tid * 3;
    int v0 = g_deg[base], v1 = g_deg[base + 1], v2 = g_deg[base + 2];
    int s = v0 + v1 + v2;
    int inc = s;
#pragma unroll
    for (int o = 1; o < 32; o <<= 1) {
        int n = __shfl_up_sync(0xffffffffu, inc, o);
        if (lane >= o) inc += n;
    }
    __shared__ int wsum[32];
    if (lane == 31) wsum[wid] = inc;
    __syncthreads();
    if (wid == 0) {
        int w = wsum[lane];
#pragma unroll
        for (int o = 1; o < 32; o <<= 1) {
            int n = __shfl_up_sync(0xffffffffu, w, o);
            if (lane >= o) w += n;
        }
        wsum[lane] = w;
    }
    __syncthreads();
    int excl = inc - s + (wid > 0 ? wsum[wid - 1] : 0);
    g_row[base + 0] = excl;
    g_row[base + 1] = excl + v0;
    g_row[base + 2] = excl + v0 + v1;
    if (tid == 1023) g_row[3072] = excl + s;
}

__global__ void scatter_kernel(const int* __restrict__ ei, int E) {
    int e = blockIdx.x * blockDim.x + threadIdx.x;
    if (e >= E) return;
    int dst = ei[E + e];
    int pos = atomicAdd(&g_cur[dst], 1);
    g_csr[g_row[dst] + pos] = ei[e];
}

// ---------------------------------------------------------------------------
// Gather: one block per dst node, thread f owns feature f. Mean included.
__global__ void gather_kernel() {
    const int n = blockIdx.x;
    const int f = threadIdx.x;
    const int start = g_row[n];
    const int deg = g_row[n + 1] - start;

    __shared__ int ssrc[256];
    float acc = 0.f;
    for (int j0 = 0; j0 < deg; j0 += 256) {
        int m = min(256, deg - j0);
        if (f < m) ssrc[f] = g_csr[start + j0 + f];
        __syncthreads();
        int j = 0;
        for (; j + 4 <= m; j += 4) {
            int s0 = ssrc[j], s1 = ssrc[j + 1], s2 = ssrc[j + 2], s3 = ssrc[j + 3];
            float a0 = g_xh[s0 * H1 + f];
            float a1 = g_xh[s1 * H1 + f];
            float a2 = g_xh[s2 * H1 + f];
            float a3 = g_xh[s3 * H1 + f];
            acc += (a0 + a1) + (a2 + a3);
        }
        for (; j < m; j++)
            acc += g_xh[ssrc[j] * H1 + f];
        __syncthreads();
    }
    g_agg[n * H1 + f] = acc / fmaxf((float)deg, 1.f);
}

// ---------------------------------------------------------------------------
// GEMM2: gate[m, j] = sum_k A[m,k] * B[k,j] + bx[j] + bh[j]
//   A[m,k] = (k<256) ? agg_mean[m,k] : xh[m,k-256]        (M=3000, K=512)
//   B[k,j] : j = gate*128 + o; (k<256) ? Wx_rel[gate,k,o] : Wx_root[gate,k-256,o]
__global__ void gemm2_kernel(const float* __restrict__ Wrel,
                             const float* __restrict__ Wroot,
                             const float* __restrict__ bx,
                             const float* __restrict__ bh) {
    __shared__ float As[16][68];
    __shared__ float Bs[16][68];
    const int bm = blockIdx.y * 64;
    const int bn = blockIdx.x * 64;                 // column-block within one gate
    const int tid = threadIdx.x;
    const int lr = tid >> 2;
    const int lk = (tid & 3) * 4;
    const int tx = tid & 15, ty = tid >> 4;
    const int gate  = bn >> 7;
    const int obase = bn & 127;

    float acc[4][4];
#pragma unroll
    for (int i = 0; i < 4; i++)
#pragma unroll
        for (int j = 0; j < 4; j++) acc[i][j] = 0.f;

    for (int k0 = 0; k0 < 2 * H1; k0 += 16) {
        float4 av = make_float4(0.f, 0.f, 0.f, 0.f);
        int gm = bm + lr;
        if (gm < N_PAD) {
            const float* Aarr = (k0 < H1) ? (g_agg + (size_t)gm * H1 + k0)
                                          : (g_xh  + (size_t)gm * H1 + (k0 - H1));
            av = *(const float4*)(Aarr + lk);
        }
        As[lk + 0][lr] = av.x; As[lk + 1][lr] = av.y;
        As[lk + 2][lr] = av.z; As[lk + 3][lr] = av.w;

        int kr = tid >> 4;            // 0..15
        int cc = (tid & 15) * 4;      // 0..60
        int kglob = k0 + kr;
        const float* Wsrc = (kglob < H1)
            ? (Wrel  + (size_t)gate * H1 * OUTD + (size_t)kglob * OUTD)
            : (Wroot + (size_t)gate * H1 * OUTD + (size_t)(kglob - H1) * OUTD);
        float4 bv = *(const float4*)(Wsrc + obase + cc);
        Bs[kr][cc + 0] = bv.x; Bs[kr][cc + 1] = bv.y;
        Bs[kr][cc + 2] = bv.z; Bs[kr][cc + 3] = bv.w;
        __syncthreads();

#pragma unroll
        for (int kk = 0; kk < 16; kk++) {
            float4 a4 = *(const float4*)&As[kk][ty * 4];
            float4 b4 = *(const float4*)&Bs[kk][tx * 4];
            float a[4] = {a4.x, a4.y, a4.z, a4.w};
            float b[4] = {b4.x, b4.y, b4.z, b4.w};
#pragma unroll
            for (int i = 0; i < 4; i++)
#pragma unroll
                for (int j = 0; j < 4; j++)
                    acc[i][j] = fmaf(a[i], b[j], acc[i][j]);
        }
        __syncthreads();
    }

#pragma unroll
    for (int i = 0; i < 4; i++) {
        int m = bm + ty * 4 + i;
        if (m >= N_PAD) continue;
#pragma unroll
        for (int j = 0; j < 4; j++) {
            int n = bn + tx * 4 + j;
            g_gate[(size_t)m * GATES_N + n] = acc[i][j] + bx[n] + bh[n];
        }
    }
}

// ---------------------------------------------------------------------------
// Gates + H + final projection. C_prev = 0 so forget gate is dead.
__global__ void finish_kernel(const float* __restrict__ fcw,
                              const float* __restrict__ fcb,
                              float* __restrict__ out,
                              float* __restrict__ Hout) {
    int n = blockIdx.x;       // 0..2999
    int o = threadIdx.x;      // 0..127
    const float* g = g_gate + (size_t)n * GATES_N;
    float gi = g[o];
    float gc = g[2 * OUTD + o];
    float go = g[3 * OUTD + o];
    float I = 1.f / (1.f + __expf(-gi));
    float T = tanhf(gc);
    float O = 1.f / (1.f + __expf(-go));
    float C = I * T;
    float H = O * tanhf(C);
    Hout[n * OUTD + o] = H;

    float v = H * fcw[o];
#pragma unroll
    for (int s = 16; s > 0; s >>= 1)
        v += __shfl_down_sync(0xffffffffu, v, s);
    __shared__ float sred[4];
    if ((o & 31) == 0) sred[o >> 5] = v;
    __syncthreads();
    if (o == 0 && n < N_REAL)
        out[n] = sred[0] + sred[1] + sred[2] + sred[3] + fcb[0];
}

// ---------------------------------------------------------------------------
extern "C" void kernel_launch(void* const* d_in, const int* in_sizes, int n_in,
                              void* d_out, int out_size) {
    const float* x      = (const float*)d_in[0];
    const int*   ei     = (const int*)  d_in[1];
    const float* fc0_w  = (const float*)d_in[2];
    const float* fc0_b  = (const float*)d_in[3];
    const float* Wx_rel = (const float*)d_in[4];
    const float* Wx_root= (const float*)d_in[5];
    const float* bx     = (const float*)d_in[6];
    // d_in[7] Wh_rel, d_in[8] Wh_root: multiplied by zero state -> unused
    const float* bh     = (const float*)d_in[9];
    const float* fc_w   = (const float*)d_in[10];
    const float* fc_b   = (const float*)d_in[11];
    const int E = in_sizes[1] / 2;

    float* out  = (float*)d_out;          // [2500]
    float* Hout = out + N_REAL;           // [3000 x 128]

    zero_kernel<<<(3072 + 255) / 256, 256>>>();

    dim3 g1(H1 / 64, (N_REAL + 63) / 64);
    gemm1_kernel<<<g1, 256>>>(x, fc0_w, fc0_b);
    pad_xh_kernel<<<((N_PAD - N_REAL) * H1 + 255) / 256, 256>>>(fc0_b);

    count_kernel<<<(E + 255) / 256, 256>>>(ei, E);
    scan_kernel<<<1, 1024>>>();
    scatter_kernel<<<(E + 255) / 256, 256>>>(ei, E);
    gather_kernel<<<N_PAD, H1>>>();

    dim3 g2(GATES_N / 64, (N_PAD + 63) / 64);
    gemm2_kernel<<<g2, 256>>>(Wx_rel, Wx_root, bx, bh);

    finish_kernel<<<N_PAD, OUTD>>>(fc_w, fc_b, out, Hout);
}

// round 5
// speedup vs baseline: 1.4478x; 1.4478x over previous
#include <cuda_runtime.h>

#define N_PAD   3000
#define N_REAL  2500
#define F_IN    1024
#define H1      256
#define OUTD    128
#define GATES_N 512   // 4 gates x 128
#define MAX_E   1048576

// Scratch (device globals — no allocation allowed)
__device__ float g_xh  [N_PAD * H1];       // relu(fc0(x_pad))
__device__ float g_agg [N_PAD * H1];       // mean-aggregated neighbors
__device__ float g_gate[N_PAD * GATES_N];  // pre-activation gates
__device__ int   g_deg [3072];             // in-degree (padded for scan)
__device__ int   g_row [3073];             // CSR row starts
__device__ int   g_cur [N_PAD];            // scatter cursors
__device__ int   g_csr [MAX_E];            // CSR column (src) indices

// ---------------------------------------------------------------------------
__device__ __forceinline__ unsigned f2tf32(float f) {
    unsigned u;
    asm("cvt.rna.tf32.f32 %0, %1;" : "=r"(u) : "f"(f));
    return u;
}

__device__ __forceinline__ void mma_tf32(float* c, const unsigned* a, const unsigned* b) {
    asm volatile(
        "mma.sync.aligned.m16n8k8.row.col.f32.tf32.tf32.f32 "
        "{%0,%1,%2,%3}, {%4,%5,%6,%7}, {%8,%9}, {%0,%1,%2,%3};\n"
        : "+f"(c[0]), "+f"(c[1]), "+f"(c[2]), "+f"(c[3])
        : "r"(a[0]), "r"(a[1]), "r"(a[2]), "r"(a[3]), "r"(b[0]), "r"(b[1]));
}

// ---------------------------------------------------------------------------
__global__ void zero_kernel() {
    int i = blockIdx.x * blockDim.x + threadIdx.x;
    if (i < 3072)  g_deg[i] = 0;
    if (i < N_PAD) g_cur[i] = 0;
}

// ---------------------------------------------------------------------------
// Shared-memory strides chosen for conflict-free fragment loads:
// As[m][k]: stride 40 -> bank(m*40+k) = 8m+k mod 32, distinct for m in 0..7, k in 0..3
// Bs[k][n]: stride 72 -> bank(k*72+n) = 8k+n mod 32, distinct for k in 0..3, n in 0..7
#define ASTRIDE 40
#define BSTRIDE 72

// GEMM1: xh[m,n] = relu(sum_k x[m,k]*w[n,k] + b[n]), m<2500, n<256, K=1024
// 64x64x32 tile, 128 threads (4 warps of 32x32 warp tiles), tf32 mma.
__global__ void gemm1_kernel(const float* __restrict__ x,
                             const float* __restrict__ w,
                             const float* __restrict__ bias) {
    __shared__ unsigned As[64 * ASTRIDE];
    __shared__ unsigned Bs[32 * BSTRIDE];
    const int bm = blockIdx.y * 64;
    const int bn = blockIdx.x * 64;
    const int tid = threadIdx.x;
    const int warp = tid >> 5, lane = tid & 31;
    const int wm = warp >> 1, wn = warp & 1;
    const int gid = lane >> 2, tig = lane & 3;

    float acc[2][4][4];
#pragma unroll
    for (int mt = 0; mt < 2; mt++)
#pragma unroll
        for (int nt = 0; nt < 4; nt++)
#pragma unroll
            for (int r = 0; r < 4; r++) acc[mt][nt][r] = 0.f;

    const int r0 = tid >> 3;        // 0..15
    const int c8 = tid & 7;         // 0..7 (float4-column)
    const int nb = tid & 63;        // 0..63 (B row = output col)
    const int cb = tid >> 6;        // 0..1

    for (int k0 = 0; k0 < F_IN; k0 += 32) {
        // Stage A: rows r0, r0+16, r0+32, r0+48; float4 at col 4*c8
#pragma unroll
        for (int rr = 0; rr < 4; rr++) {
            int row = r0 + rr * 16;
            int gm = bm + row;
            float4 v = make_float4(0.f, 0.f, 0.f, 0.f);
            if (gm < N_REAL)
                v = *(const float4*)(x + (size_t)gm * F_IN + k0 + 4 * c8);
            uint4 u = make_uint4(f2tf32(v.x), f2tf32(v.y), f2tf32(v.z), f2tf32(v.w));
            *(uint4*)&As[row * ASTRIDE + 4 * c8] = u;
        }
        // Stage B transposed: Bs[k][n] = w[bn+n][k0+k]
#pragma unroll
        for (int i = 0; i < 4; i++) {
            int c = cb * 4 + i;   // 0..7
            float4 v = *(const float4*)(w + (size_t)(bn + nb) * F_IN + k0 + 4 * c);
            Bs[(4 * c + 0) * BSTRIDE + nb] = f2tf32(v.x);
            Bs[(4 * c + 1) * BSTRIDE + nb] = f2tf32(v.y);
            Bs[(4 * c + 2) * BSTRIDE + nb] = f2tf32(v.z);
            Bs[(4 * c + 3) * BSTRIDE + nb] = f2tf32(v.w);
        }
        __syncthreads();

#pragma unroll
        for (int ks = 0; ks < 4; ks++) {
            int kk = ks * 8;
            unsigned a[2][4], b[4][2];
#pragma unroll
            for (int mt = 0; mt < 2; mt++) {
                int ar = wm * 32 + mt * 16;
                a[mt][0] = As[(ar + gid) * ASTRIDE + kk + tig];
                a[mt][1] = As[(ar + gid + 8) * ASTRIDE + kk + tig];
                a[mt][2] = As[(ar + gid) * ASTRIDE + kk + tig + 4];
                a[mt][3] = As[(ar + gid + 8) * ASTRIDE + kk + tig + 4];
            }
#pragma unroll
            for (int nt = 0; nt < 4; nt++) {
                int nc = wn * 32 + nt * 8 + gid;
                b[nt][0] = Bs[(kk + tig) * BSTRIDE + nc];
                b[nt][1] = Bs[(kk + tig + 4) * BSTRIDE + nc];
            }
#pragma unroll
            for (int mt = 0; mt < 2; mt++)
#pragma unroll
                for (int nt = 0; nt < 4; nt++)
                    mma_tf32(acc[mt][nt], a[mt], b[nt]);
        }
        __syncthreads();
    }

#pragma unroll
    for (int mt = 0; mt < 2; mt++) {
        int mrow0 = bm + wm * 32 + mt * 16 + gid;
#pragma unroll
        for (int nt = 0; nt < 4; nt++) {
            int ncol = bn + wn * 32 + nt * 8 + 2 * tig;
            float b0 = bias[ncol], b1 = bias[ncol + 1];
            if (mrow0 < N_REAL) {
                float v0 = acc[mt][nt][0] + b0, v1 = acc[mt][nt][1] + b1;
                g_xh[mrow0 * H1 + ncol]     = v0 > 0.f ? v0 : 0.f;
                g_xh[mrow0 * H1 + ncol + 1] = v1 > 0.f ? v1 : 0.f;
            }
            if (mrow0 + 8 < N_REAL) {
                float v2 = acc[mt][nt][2] + b0, v3 = acc[mt][nt][3] + b1;
                g_xh[(mrow0 + 8) * H1 + ncol]     = v2 > 0.f ? v2 : 0.f;
                g_xh[(mrow0 + 8) * H1 + ncol + 1] = v3 > 0.f ? v3 : 0.f;
            }
        }
    }
}

// Rows 2500..2999 of x_pad are zero -> xh row = relu(fc0_b)
__global__ void pad_xh_kernel(const float* __restrict__ bias) {
    int i = blockIdx.x * blockDim.x + threadIdx.x;
    if (i >= (N_PAD - N_REAL) * H1) return;
    float v = bias[i & (H1 - 1)];
    g_xh[N_REAL * H1 + i] = v > 0.f ? v : 0.f;
}

// ---------------------------------------------------------------------------
// CSR build (4 edges per thread, int4 loads for MLP)
__global__ void count_kernel(const int* __restrict__ ei, int E) {
    int t = blockIdx.x * blockDim.x + threadIdx.x;
    int e = t * 4;
    if (e >= E) return;
    if (e + 3 < E) {
        int4 d = *(const int4*)(ei + E + e);
        atomicAdd(&g_deg[d.x], 1);
        atomicAdd(&g_deg[d.y], 1);
        atomicAdd(&g_deg[d.z], 1);
        atomicAdd(&g_deg[d.w], 1);
    } else {
        for (int j = e; j < E; j++) atomicAdd(&g_deg[ei[E + j]], 1);
    }
}

// Exclusive scan over 3072 degrees: single block of 1024 threads, 3 elems each.
__global__ void scan_kernel() {
    const int tid = threadIdx.x;
    const int lane = tid & 31, wid = tid >> 5;
    int base = tid * 3;
    int v0 = g_deg[base], v1 = g_deg[base + 1], v2 = g_deg[base + 2];
    int s = v0 + v1 + v2;
    int inc = s;
#pragma unroll
    for (int o = 1; o < 32; o <<= 1) {
        int n = __shfl_up_sync(0xffffffffu, inc, o);
        if (lane >= o) inc += n;
    }
    __shared__ int wsum[32];
    if (lane == 31) wsum[wid] = inc;
    __syncthreads();
    if (wid == 0) {
        int w = wsum[lane];
#pragma unroll
        for (int o = 1; o < 32; o <<= 1) {
            int n = __shfl_up_sync(0xffffffffu, w, o);
            if (lane >= o) w += n;
        }
        wsum[lane] = w;
    }
    __syncthreads();
    int excl = inc - s + (wid > 0 ? wsum[wid - 1] : 0);
    g_row[base + 0] = excl;
    g_row[base + 1] = excl + v0;
    g_row[base + 2] = excl + v0 + v1;
    if (tid == 1023) g_row[3072] = excl + s;
}

__global__ void scatter_kernel(const int* __restrict__ ei, int E) {
    int t = blockIdx.x * blockDim.x + threadIdx.x;
    int e = t * 4;
    if (e >= E) return;
    if (e + 3 < E) {
        int4 s = *(const int4*)(ei + e);
        int4 d = *(const int4*)(ei + E + e);
        int p0 = atomicAdd(&g_cur[d.x], 1); g_csr[g_row[d.x] + p0] = s.x;
        int p1 = atomicAdd(&g_cur[d.y], 1); g_csr[g_row[d.y] + p1] = s.y;
        int p2 = atomicAdd(&g_cur[d.z], 1); g_csr[g_row[d.z] + p2] = s.z;
        int p3 = atomicAdd(&g_cur[d.w], 1); g_csr[g_row[d.w] + p3] = s.w;
    } else {
        for (int j = e; j < E; j++) {
            int dst = ei[E + j];
            int pos = atomicAdd(&g_cur[dst], 1);
            g_csr[g_row[dst] + pos] = ei[j];
        }
    }
}

// ---------------------------------------------------------------------------
// Gather: one block per dst node, thread f owns feature f. Mean included.
__global__ void gather_kernel() {
    const int n = blockIdx.x;
    const int f = threadIdx.x;
    const int start = g_row[n];
    const int deg = g_row[n + 1] - start;

    __shared__ int ssrc[256];
    float acc = 0.f;
    for (int j0 = 0; j0 < deg; j0 += 256) {
        int m = min(256, deg - j0);
        if (f < m) ssrc[f] = g_csr[start + j0 + f];
        __syncthreads();
        int j = 0;
        for (; j + 4 <= m; j += 4) {
            int s0 = ssrc[j], s1 = ssrc[j + 1], s2 = ssrc[j + 2], s3 = ssrc[j + 3];
            float a0 = g_xh[s0 * H1 + f];
            float a1 = g_xh[s1 * H1 + f];
            float a2 = g_xh[s2 * H1 + f];
            float a3 = g_xh[s3 * H1 + f];
            acc += (a0 + a1) + (a2 + a3);
        }
        for (; j < m; j++)
            acc += g_xh[ssrc[j] * H1 + f];
        __syncthreads();
    }
    g_agg[n * H1 + f] = acc / fmaxf((float)deg, 1.f);
}

// ---------------------------------------------------------------------------
// GEMM2 (tf32): gate[m, j] = sum_k A[m,k]*B[k,j] + bx[j] + bh[j]
//   A[m,k] = (k<256) ? agg[m,k] : xh[m,k-256]   (M=3000, K=512)
//   B[k,j], j = gate*128+o: (k<256) ? Wx_rel[gate,k,o] : Wx_root[gate,k-256,o]
__global__ void gemm2_kernel(const float* __restrict__ Wrel,
                             const float* __restrict__ Wroot,
                             const float* __restrict__ bx,
                             const float* __restrict__ bh) {
    __shared__ unsigned As[64 * ASTRIDE];
    __shared__ unsigned Bs[32 * BSTRIDE];
    const int bm = blockIdx.y * 64;
    const int bn = blockIdx.x * 64;
    const int tid = threadIdx.x;
    const int warp = tid >> 5, lane = tid & 31;
    const int wm = warp >> 1, wn = warp & 1;
    const int gid = lane >> 2, tig = lane & 3;
    const int gate = bn >> 7;
    const int obase = bn & 127;

    float acc[2][4][4];
#pragma unroll
    for (int mt = 0; mt < 2; mt++)
#pragma unroll
        for (int nt = 0; nt < 4; nt++)
#pragma unroll
            for (int r = 0; r < 4; r++) acc[mt][nt][r] = 0.f;

    const int r0 = tid >> 3;
    const int c8 = tid & 7;
    const int ob = tid & 63;
    const int kc = tid >> 6;     // 0..1

    for (int k0 = 0; k0 < 2 * H1; k0 += 32) {
        // Stage A (K blocks never straddle the 256 boundary since 32 | 256)
        const float* Abase = (k0 < H1) ? (g_agg + k0) : (g_xh + (k0 - H1));
#pragma unroll
        for (int rr = 0; rr < 4; rr++) {
            int row = r0 + rr * 16;
            int gm = bm + row;
            float4 v = make_float4(0.f, 0.f, 0.f, 0.f);
            if (gm < N_PAD)
                v = *(const float4*)(Abase + (size_t)gm * H1 + 4 * c8);
            uint4 u = make_uint4(f2tf32(v.x), f2tf32(v.y), f2tf32(v.z), f2tf32(v.w));
            *(uint4*)&As[row * ASTRIDE + 4 * c8] = u;
        }
        // Stage B: Bs[k][o_l] = Wsrc[k0+k][obase+o_l]
        const float* Wbase = (k0 < H1)
            ? (Wrel  + (size_t)gate * H1 * OUTD + (size_t)k0 * OUTD + obase)
            : (Wroot + (size_t)gate * H1 * OUTD + (size_t)(k0 - H1) * OUTD + obase);
#pragma unroll
        for (int i = 0; i < 16; i++) {
            int k = kc * 16 + i;
            Bs[k * BSTRIDE + ob] = f2tf32(Wbase[(size_t)k * OUTD + ob]);
        }
        __syncthreads();

#pragma unroll
        for (int ks = 0; ks < 4; ks++) {
            int kk = ks * 8;
            unsigned a[2][4], b[4][2];
#pragma unroll
            for (int mt = 0; mt < 2; mt++) {
                int ar = wm * 32 + mt * 16;
                a[mt][0] = As[(ar + gid) * ASTRIDE + kk + tig];
                a[mt][1] = As[(ar + gid + 8) * ASTRIDE + kk + tig];
                a[mt][2] = As[(ar + gid) * ASTRIDE + kk + tig + 4];
                a[mt][3] = As[(ar + gid + 8) * ASTRIDE + kk + tig + 4];
            }
#pragma unroll
            for (int nt = 0; nt < 4; nt++) {
                int nc = wn * 32 + nt * 8 + gid;
                b[nt][0] = Bs[(kk + tig) * BSTRIDE + nc];
                b[nt][1] = Bs[(kk + tig + 4) * BSTRIDE + nc];
            }
#pragma unroll
            for (int mt = 0; mt < 2; mt++)
#pragma unroll
                for (int nt = 0; nt < 4; nt++)
                    mma_tf32(acc[mt][nt], a[mt], b[nt]);
        }
        __syncthreads();
    }

#pragma unroll
    for (int mt = 0; mt < 2; mt++) {
        int mrow0 = bm + wm * 32 + mt * 16 + gid;
#pragma unroll
        for (int nt = 0; nt < 4; nt++) {
            int ncol = bn + wn * 32 + nt * 8 + 2 * tig;      // global gate col
            float b0 = bx[ncol] + bh[ncol];
            float b1 = bx[ncol + 1] + bh[ncol + 1];
            if (mrow0 < N_PAD) {
                g_gate[(size_t)mrow0 * GATES_N + ncol]     = acc[mt][nt][0] + b0;
                g_gate[(size_t)mrow0 * GATES_N + ncol + 1] = acc[mt][nt][1] + b1;
            }
            if (mrow0 + 8 < N_PAD) {
                g_gate[(size_t)(mrow0 + 8) * GATES_N + ncol]     = acc[mt][nt][2] + b0;
                g_gate[(size_t)(mrow0 + 8) * GATES_N + ncol + 1] = acc[mt][nt][3] + b1;
            }
        }
    }
}

// ---------------------------------------------------------------------------
// Gates + H + final projection. C_prev = 0 so forget gate is dead.
__global__ void finish_kernel(const float* __restrict__ fcw,
                              const float* __restrict__ fcb,
                              float* __restrict__ out,
                              float* __restrict__ Hout) {
    int n = blockIdx.x;       // 0..2999
    int o = threadIdx.x;      // 0..127
    const float* g = g_gate + (size_t)n * GATES_N;
    float gi = g[o];
    float gc = g[2 * OUTD + o];
    float go = g[3 * OUTD + o];
    float I = 1.f / (1.f + __expf(-gi));
    float T = tanhf(gc);
    float O = 1.f / (1.f + __expf(-go));
    float C = I * T;
    float H = O * tanhf(C);
    Hout[n * OUTD + o] = H;

    float v = H * fcw[o];
#pragma unroll
    for (int s = 16; s > 0; s >>= 1)
        v += __shfl_down_sync(0xffffffffu, v, s);
    __shared__ float sred[4];
    if ((o & 31) == 0) sred[o >> 5] = v;
    __syncthreads();
    if (o == 0 && n < N_REAL)
        out[n] = sred[0] + sred[1] + sred[2] + sred[3] + fcb[0];
}

// ---------------------------------------------------------------------------
extern "C" void kernel_launch(void* const* d_in, const int* in_sizes, int n_in,
                              void* d_out, int out_size) {
    const float* x      = (const float*)d_in[0];
    const int*   ei     = (const int*)  d_in[1];
    const float* fc0_w  = (const float*)d_in[2];
    const float* fc0_b  = (const float*)d_in[3];
    const float* Wx_rel = (const float*)d_in[4];
    const float* Wx_root= (const float*)d_in[5];
    const float* bx     = (const float*)d_in[6];
    // d_in[7] Wh_rel, d_in[8] Wh_root: multiplied by zero state -> unused
    const float* bh     = (const float*)d_in[9];
    const float* fc_w   = (const float*)d_in[10];
    const float* fc_b   = (const float*)d_in[11];
    const int E = in_sizes[1] / 2;

    float* out  = (float*)d_out;          // [2500]
    float* Hout = out + N_REAL;           // [3000 x 128]

    zero_kernel<<<(3072 + 255) / 256, 256>>>();

    dim3 g1(H1 / 64, (N_REAL + 63) / 64);          // 4 x 40
    gemm1_kernel<<<g1, 128>>>(x, fc0_w, fc0_b);
    pad_xh_kernel<<<((N_PAD - N_REAL) * H1 + 255) / 256, 256>>>(fc0_b);

    int q = (E + 3) / 4;
    count_kernel<<<(q + 255) / 256, 256>>>(ei, E);
    scan_kernel<<<1, 1024>>>();
    scatter_kernel<<<(q + 255) / 256, 256>>>(ei, E);
    gather_kernel<<<N_PAD, H1>>>();

    dim3 g2(GATES_N / 64, (N_PAD + 63) / 64);      // 8 x 47
    gemm2_kernel<<<g2, 128>>>(Wx_rel, Wx_root, bx, bh);

    finish_kernel<<<N_PAD, OUTD>>>(fc_w, fc_b, out, Hout);
}

// round 6
// speedup vs baseline: 1.6162x; 1.1164x over previous
#include <cuda_runtime.h>

#define N_PAD   3000
#define N_REAL  2500
#define F_IN    1024
#define H1      256
#define OUTD    128
#define GATES_N 512   // 4 gates x 128
#define MAX_E   1048576

// Scratch (device globals — no allocation allowed)
__device__ float g_xh  [N_PAD * H1];       // relu(fc0(x_pad))
__device__ float g_agg [N_PAD * H1];       // mean-aggregated neighbors
__device__ float g_gate[N_PAD * GATES_N];  // pre-activation gates
__device__ int   g_deg [3072];             // in-degree (padded for scan)
__device__ int   g_row [3073];             // CSR row starts
__device__ int   g_cur [N_PAD];            // scatter cursors
__device__ int   g_csr [MAX_E];            // CSR column (src) indices

// ---------------------------------------------------------------------------
__device__ __forceinline__ unsigned f2tf32(float f) {
    unsigned u;
    asm("cvt.rna.tf32.f32 %0, %1;" : "=r"(u) : "f"(f));
    return u;
}

__device__ __forceinline__ void mma_tf32(float* c, const unsigned* a, const unsigned* b) {
    asm volatile(
        "mma.sync.aligned.m16n8k8.row.col.f32.tf32.tf32.f32 "
        "{%0,%1,%2,%3}, {%4,%5,%6,%7}, {%8,%9}, {%0,%1,%2,%3};\n"
        : "+f"(c[0]), "+f"(c[1]), "+f"(c[2]), "+f"(c[3])
        : "r"(a[0]), "r"(a[1]), "r"(a[2]), "r"(a[3]), "r"(b[0]), "r"(b[1]));
}

// ---------------------------------------------------------------------------
// init: zero deg/cur counters AND write xh pad rows (rows 2500..2999 of x_pad
// are zero -> xh row = relu(fc0_b)).  One launch instead of two.
__global__ void init_kernel(const float* __restrict__ bias) {
    int i = blockIdx.x * blockDim.x + threadIdx.x;
    if (i < 3072)  g_deg[i] = 0;
    if (i < N_PAD) g_cur[i] = 0;
    if (i < (N_PAD - N_REAL) * H1) {
        float v = bias[i & (H1 - 1)];
        g_xh[N_REAL * H1 + i] = v > 0.f ? v : 0.f;
    }
}

// ---------------------------------------------------------------------------
// Shared-memory strides chosen for conflict-free fragment loads:
// As[m][k]: stride 40 -> bank(m*40+k) = 8m+k mod 32, distinct for m in 0..7, k in 0..3
// Bs[k][n]: stride 72 -> bank(k*72+n) = 8k+n mod 32, distinct for k in 0..3, n in 0..7
#define ASTRIDE 40
#define BSTRIDE 72

// GEMM1: xh[m,n] = relu(sum_k x[m,k]*w[n,k] + b[n]), m<2500, n<256, K=1024
// 64x64x32 tile, 128 threads (4 warps of 32x32 warp tiles), tf32 mma.
__global__ void gemm1_kernel(const float* __restrict__ x,
                             const float* __restrict__ w,
                             const float* __restrict__ bias) {
    __shared__ unsigned As[64 * ASTRIDE];
    __shared__ unsigned Bs[32 * BSTRIDE];
    const int bm = blockIdx.y * 64;
    const int bn = blockIdx.x * 64;
    const int tid = threadIdx.x;
    const int warp = tid >> 5, lane = tid & 31;
    const int wm = warp >> 1, wn = warp & 1;
    const int gid = lane >> 2, tig = lane & 3;

    float acc[2][4][4];
#pragma unroll
    for (int mt = 0; mt < 2; mt++)
#pragma unroll
        for (int nt = 0; nt < 4; nt++)
#pragma unroll
            for (int r = 0; r < 4; r++) acc[mt][nt][r] = 0.f;

    const int r0 = tid >> 3;        // 0..15
    const int c8 = tid & 7;         // 0..7 (float4-column)
    const int nb = tid & 63;        // 0..63 (B row = output col)
    const int cb = tid >> 6;        // 0..1

    for (int k0 = 0; k0 < F_IN; k0 += 32) {
        // Stage A: rows r0, r0+16, r0+32, r0+48; float4 at col 4*c8
#pragma unroll
        for (int rr = 0; rr < 4; rr++) {
            int row = r0 + rr * 16;
            int gm = bm + row;
            float4 v = make_float4(0.f, 0.f, 0.f, 0.f);
            if (gm < N_REAL)
                v = *(const float4*)(x + (size_t)gm * F_IN + k0 + 4 * c8);
            uint4 u = make_uint4(f2tf32(v.x), f2tf32(v.y), f2tf32(v.z), f2tf32(v.w));
            *(uint4*)&As[row * ASTRIDE + 4 * c8] = u;
        }
        // Stage B transposed: Bs[k][n] = w[bn+n][k0+k]
#pragma unroll
        for (int i = 0; i < 4; i++) {
            int c = cb * 4 + i;   // 0..7
            float4 v = *(const float4*)(w + (size_t)(bn + nb) * F_IN + k0 + 4 * c);
            Bs[(4 * c + 0) * BSTRIDE + nb] = f2tf32(v.x);
            Bs[(4 * c + 1) * BSTRIDE + nb] = f2tf32(v.y);
            Bs[(4 * c + 2) * BSTRIDE + nb] = f2tf32(v.z);
            Bs[(4 * c + 3) * BSTRIDE + nb] = f2tf32(v.w);
        }
        __syncthreads();

#pragma unroll
        for (int ks = 0; ks < 4; ks++) {
            int kk = ks * 8;
            unsigned a[2][4], b[4][2];
#pragma unroll
            for (int mt = 0; mt < 2; mt++) {
                int ar = wm * 32 + mt * 16;
                a[mt][0] = As[(ar + gid) * ASTRIDE + kk + tig];
                a[mt][1] = As[(ar + gid + 8) * ASTRIDE + kk + tig];
                a[mt][2] = As[(ar + gid) * ASTRIDE + kk + tig + 4];
                a[mt][3] = As[(ar + gid + 8) * ASTRIDE + kk + tig + 4];
            }
#pragma unroll
            for (int nt = 0; nt < 4; nt++) {
                int nc = wn * 32 + nt * 8 + gid;
                b[nt][0] = Bs[(kk + tig) * BSTRIDE + nc];
                b[nt][1] = Bs[(kk + tig + 4) * BSTRIDE + nc];
            }
#pragma unroll
            for (int mt = 0; mt < 2; mt++)
#pragma unroll
                for (int nt = 0; nt < 4; nt++)
                    mma_tf32(acc[mt][nt], a[mt], b[nt]);
        }
        __syncthreads();
    }

#pragma unroll
    for (int mt = 0; mt < 2; mt++) {
        int mrow0 = bm + wm * 32 + mt * 16 + gid;
#pragma unroll
        for (int nt = 0; nt < 4; nt++) {
            int ncol = bn + wn * 32 + nt * 8 + 2 * tig;
            float b0 = bias[ncol], b1 = bias[ncol + 1];
            if (mrow0 < N_REAL) {
                float v0 = acc[mt][nt][0] + b0, v1 = acc[mt][nt][1] + b1;
                g_xh[mrow0 * H1 + ncol]     = v0 > 0.f ? v0 : 0.f;
                g_xh[mrow0 * H1 + ncol + 1] = v1 > 0.f ? v1 : 0.f;
            }
            if (mrow0 + 8 < N_REAL) {
                float v2 = acc[mt][nt][2] + b0, v3 = acc[mt][nt][3] + b1;
                g_xh[(mrow0 + 8) * H1 + ncol]     = v2 > 0.f ? v2 : 0.f;
                g_xh[(mrow0 + 8) * H1 + ncol + 1] = v3 > 0.f ? v3 : 0.f;
            }
        }
    }
}

// ---------------------------------------------------------------------------
// CSR build.  count: per-block smem histogram -> coalesced RED merge.
// Kills the 100-ops-per-address L2 atomic serialization of the naive version.
__global__ void count_kernel(const int* __restrict__ ei, int E) {
    __shared__ int hcnt[3008];
    for (int i = threadIdx.x; i < 3008; i += blockDim.x) hcnt[i] = 0;
    __syncthreads();

    int q = (E + 3) >> 2;
    int stride = gridDim.x * blockDim.x;
    for (int t = blockIdx.x * blockDim.x + threadIdx.x; t < q; t += stride) {
        int e = t * 4;
        if (e + 3 < E) {
            int4 d = *(const int4*)(ei + E + e);
            atomicAdd(&hcnt[d.x], 1);
            atomicAdd(&hcnt[d.y], 1);
            atomicAdd(&hcnt[d.z], 1);
            atomicAdd(&hcnt[d.w], 1);
        } else {
            for (int j = e; j < E; j++) atomicAdd(&hcnt[ei[E + j]], 1);
        }
    }
    __syncthreads();
    for (int i = threadIdx.x; i < 3000; i += blockDim.x) {
        int c = hcnt[i];
        if (c) atomicAdd(&g_deg[i], c);
    }
}

// Exclusive scan over 3072 degrees: single block of 1024 threads, 3 elems each.
__global__ void scan_kernel() {
    const int tid = threadIdx.x;
    const int lane = tid & 31, wid = tid >> 5;
    int base = tid * 3;
    int v0 = g_deg[base], v1 = g_deg[base + 1], v2 = g_deg[base + 2];
    int s = v0 + v1 + v2;
    int inc = s;
#pragma unroll
    for (int o = 1; o < 32; o <<= 1) {
        int n = __shfl_up_sync(0xffffffffu, inc, o);
        if (lane >= o) inc += n;
    }
    __shared__ int wsum[32];
    if (lane == 31) wsum[wid] = inc;
    __syncthreads();
    if (wid == 0) {
        int w = wsum[lane];
#pragma unroll
        for (int o = 1; o < 32; o <<= 1) {
            int n = __shfl_up_sync(0xffffffffu, w, o);
            if (lane >= o) w += n;
        }
        wsum[lane] = w;
    }
    __syncthreads();
    int excl = inc - s + (wid > 0 ? wsum[wid - 1] : 0);
    g_row[base + 0] = excl;
    g_row[base + 1] = excl + v0;
    g_row[base + 2] = excl + v0 + v1;
    if (tid == 1023) g_row[3072] = excl + s;
}

__global__ void scatter_kernel(const int* __restrict__ ei, int E) {
    int t = blockIdx.x * blockDim.x + threadIdx.x;
    int e = t * 4;
    if (e >= E) return;
    if (e + 3 < E) {
        int4 s = *(const int4*)(ei + e);
        int4 d = *(const int4*)(ei + E + e);
        int p0 = atomicAdd(&g_cur[d.x], 1); g_csr[g_row[d.x] + p0] = s.x;
        int p1 = atomicAdd(&g_cur[d.y], 1); g_csr[g_row[d.y] + p1] = s.y;
        int p2 = atomicAdd(&g_cur[d.z], 1); g_csr[g_row[d.z] + p2] = s.z;
        int p3 = atomicAdd(&g_cur[d.w], 1); g_csr[g_row[d.w] + p3] = s.w;
    } else {
        for (int j = e; j < E; j++) {
            int dst = ei[E + j];
            int pos = atomicAdd(&g_cur[dst], 1);
            g_csr[g_row[dst] + pos] = ei[j];
        }
    }
}

// ---------------------------------------------------------------------------
// Gather: one 64-thread block per dst node; thread t owns float4 features
// [4t, 4t+4).  4-edge unroll -> 4 outstanding LDG.128 per thread.
__global__ void gather_kernel() {
    const int n = blockIdx.x;
    const int t = threadIdx.x;        // 0..63
    const int start = g_row[n];
    const int deg = g_row[n + 1] - start;

    __shared__ int ssrc[64];
    float4 acc = make_float4(0.f, 0.f, 0.f, 0.f);
    for (int j0 = 0; j0 < deg; j0 += 64) {
        int m = min(64, deg - j0);
        if (t < m) ssrc[t] = g_csr[start + j0 + t];
        __syncthreads();
        int j = 0;
        for (; j + 4 <= m; j += 4) {
            const float4 a0 = *(const float4*)(g_xh + ssrc[j]     * H1 + 4 * t);
            const float4 a1 = *(const float4*)(g_xh + ssrc[j + 1] * H1 + 4 * t);
            const float4 a2 = *(const float4*)(g_xh + ssrc[j + 2] * H1 + 4 * t);
            const float4 a3 = *(const float4*)(g_xh + ssrc[j + 3] * H1 + 4 * t);
            acc.x += (a0.x + a1.x) + (a2.x + a3.x);
            acc.y += (a0.y + a1.y) + (a2.y + a3.y);
            acc.z += (a0.z + a1.z) + (a2.z + a3.z);
            acc.w += (a0.w + a1.w) + (a2.w + a3.w);
        }
        for (; j < m; j++) {
            const float4 a = *(const float4*)(g_xh + ssrc[j] * H1 + 4 * t);
            acc.x += a.x; acc.y += a.y; acc.z += a.z; acc.w += a.w;
        }
        __syncthreads();
    }
    float inv = 1.f / fmaxf((float)deg, 1.f);
    acc.x *= inv; acc.y *= inv; acc.z *= inv; acc.w *= inv;
    *(float4*)(g_agg + n * H1 + 4 * t) = acc;
}

// ---------------------------------------------------------------------------
// GEMM2 (tf32): gate[m, j] = sum_k A[m,k]*B[k,j] + bx[j] + bh[j]
//   A[m,k] = (k<256) ? agg[m,k] : xh[m,k-256]   (M=3000, K=512)
//   B[k,j], j = gate*128+o: (k<256) ? Wx_rel[gate,k,o] : Wx_root[gate,k-256,o]
__global__ void gemm2_kernel(const float* __restrict__ Wrel,
                             const float* __restrict__ Wroot,
                             const float* __restrict__ bx,
                             const float* __restrict__ bh) {
    __shared__ unsigned As[64 * ASTRIDE];
    __shared__ unsigned Bs[32 * BSTRIDE];
    const int bm = blockIdx.y * 64;
    const int bn = blockIdx.x * 64;
    const int tid = threadIdx.x;
    const int warp = tid >> 5, lane = tid & 31;
    const int wm = warp >> 1, wn = warp & 1;
    const int gid = lane >> 2, tig = lane & 3;
    const int gate = bn >> 7;
    const int obase = bn & 127;

    float acc[2][4][4];
#pragma unroll
    for (int mt = 0; mt < 2; mt++)
#pragma unroll
        for (int nt = 0; nt < 4; nt++)
#pragma unroll
            for (int r = 0; r < 4; r++) acc[mt][nt][r] = 0.f;

    const int r0 = tid >> 3;
    const int c8 = tid & 7;
    const int ob = tid & 63;
    const int kc = tid >> 6;     // 0..1

    for (int k0 = 0; k0 < 2 * H1; k0 += 32) {
        // Stage A (K blocks never straddle the 256 boundary since 32 | 256)
        const float* Abase = (k0 < H1) ? (g_agg + k0) : (g_xh + (k0 - H1));
#pragma unroll
        for (int rr = 0; rr < 4; rr++) {
            int row = r0 + rr * 16;
            int gm = bm + row;
            float4 v = make_float4(0.f, 0.f, 0.f, 0.f);
            if (gm < N_PAD)
                v = *(const float4*)(Abase + (size_t)gm * H1 + 4 * c8);
            uint4 u = make_uint4(f2tf32(v.x), f2tf32(v.y), f2tf32(v.z), f2tf32(v.w));
            *(uint4*)&As[row * ASTRIDE + 4 * c8] = u;
        }
        // Stage B: Bs[k][o_l] = Wsrc[k0+k][obase+o_l]
        const float* Wbase = (k0 < H1)
            ? (Wrel  + (size_t)gate * H1 * OUTD + (size_t)k0 * OUTD + obase)
            : (Wroot + (size_t)gate * H1 * OUTD + (size_t)(k0 - H1) * OUTD + obase);
#pragma unroll
        for (int i = 0; i < 16; i++) {
            int k = kc * 16 + i;
            Bs[k * BSTRIDE + ob] = f2tf32(Wbase[(size_t)k * OUTD + ob]);
        }
        __syncthreads();

#pragma unroll
        for (int ks = 0; ks < 4; ks++) {
            int kk = ks * 8;
            unsigned a[2][4], b[4][2];
#pragma unroll
            for (int mt = 0; mt < 2; mt++) {
                int ar = wm * 32 + mt * 16;
                a[mt][0] = As[(ar + gid) * ASTRIDE + kk + tig];
                a[mt][1] = As[(ar + gid + 8) * ASTRIDE + kk + tig];
                a[mt][2] = As[(ar + gid) * ASTRIDE + kk + tig + 4];
                a[mt][3] = As[(ar + gid + 8) * ASTRIDE + kk + tig + 4];
            }
#pragma unroll
            for (int nt = 0; nt < 4; nt++) {
                int nc = wn * 32 + nt * 8 + gid;
                b[nt][0] = Bs[(kk + tig) * BSTRIDE + nc];
                b[nt][1] = Bs[(kk + tig + 4) * BSTRIDE + nc];
            }
#pragma unroll
            for (int mt = 0; mt < 2; mt++)
#pragma unroll
                for (int nt = 0; nt < 4; nt++)
                    mma_tf32(acc[mt][nt], a[mt], b[nt]);
        }
        __syncthreads();
    }

#pragma unroll
    for (int mt = 0; mt < 2; mt++) {
        int mrow0 = bm + wm * 32 + mt * 16 + gid;
#pragma unroll
        for (int nt = 0; nt < 4; nt++) {
            int ncol = bn + wn * 32 + nt * 8 + 2 * tig;      // global gate col
            float b0 = bx[ncol] + bh[ncol];
            float b1 = bx[ncol + 1] + bh[ncol + 1];
            if (mrow0 < N_PAD) {
                g_gate[(size_t)mrow0 * GATES_N + ncol]     = acc[mt][nt][0] + b0;
                g_gate[(size_t)mrow0 * GATES_N + ncol + 1] = acc[mt][nt][1] + b1;
            }
            if (mrow0 + 8 < N_PAD) {
                g_gate[(size_t)(mrow0 + 8) * GATES_N + ncol]     = acc[mt][nt][2] + b0;
                g_gate[(size_t)(mrow0 + 8) * GATES_N + ncol + 1] = acc[mt][nt][3] + b1;
            }
        }
    }
}

// ---------------------------------------------------------------------------
// Gates + H + final projection. C_prev = 0 so forget gate is dead.
__global__ void finish_kernel(const float* __restrict__ fcw,
                              const float* __restrict__ fcb,
                              float* __restrict__ out,
                              float* __restrict__ Hout) {
    int n = blockIdx.x;       // 0..2999
    int o = threadIdx.x;      // 0..127
    const float* g = g_gate + (size_t)n * GATES_N;
    float gi = g[o];
    float gc = g[2 * OUTD + o];
    float go = g[3 * OUTD + o];
    float I = 1.f / (1.f + __expf(-gi));
    float T = tanhf(gc);
    float O = 1.f / (1.f + __expf(-go));
    float C = I * T;
    float H = O * tanhf(C);
    Hout[n * OUTD + o] = H;

    float v = H * fcw[o];
#pragma unroll
    for (int s = 16; s > 0; s >>= 1)
        v += __shfl_down_sync(0xffffffffu, v, s);
    __shared__ float sred[4];
    if ((o & 31) == 0) sred[o >> 5] = v;
    __syncthreads();
    if (o == 0 && n < N_REAL)
        out[n] = sred[0] + sred[1] + sred[2] + sred[3] + fcb[0];
}

// ---------------------------------------------------------------------------
extern "C" void kernel_launch(void* const* d_in, const int* in_sizes, int n_in,
                              void* d_out, int out_size) {
    const float* x      = (const float*)d_in[0];
    const int*   ei     = (const int*)  d_in[1];
    const float* fc0_w  = (const float*)d_in[2];
    const float* fc0_b  = (const float*)d_in[3];
    const float* Wx_rel = (const float*)d_in[4];
    const float* Wx_root= (const float*)d_in[5];
    const float* bx     = (const float*)d_in[6];
    // d_in[7] Wh_rel, d_in[8] Wh_root: multiplied by zero state -> unused
    const float* bh     = (const float*)d_in[9];
    const float* fc_w   = (const float*)d_in[10];
    const float* fc_b   = (const float*)d_in[11];
    const int E = in_sizes[1] / 2;

    float* out  = (float*)d_out;          // [2500]
    float* Hout = out + N_REAL;           // [3000 x 128]

    init_kernel<<<((N_PAD - N_REAL) * H1 + 255) / 256, 256>>>(fc0_b);

    dim3 g1(H1 / 64, (N_REAL + 63) / 64);          // 4 x 40
    gemm1_kernel<<<g1, 128>>>(x, fc0_w, fc0_b);

    count_kernel<<<96, 512>>>(ei, E);
    scan_kernel<<<1, 1024>>>();
    int q = (E + 3) / 4;
    scatter_kernel<<<(q + 255) / 256, 256>>>(ei, E);
    gather_kernel<<<N_PAD, 64>>>();

    dim3 g2(GATES_N / 64, (N_PAD + 63) / 64);      // 8 x 47
    gemm2_kernel<<<g2, 128>>>(Wx_rel, Wx_root, bx, bh);

    finish_kernel<<<N_PAD, OUTD>>>(fc_w, fc_b, out, Hout);
}

// round 7
// speedup vs baseline: 1.6493x; 1.0205x over previous
#include <cuda_runtime.h>

#define N_PAD   3000
#define N_REAL  2500
#define F_IN    1024
#define H1      256
#define OUTD    128
#define GATES_N 512   // 4 gates x 128
#define MAX_E   1048576
#define CNT_BLOCKS 48
#define SCT_BLOCKS 32

// Scratch (device globals — no allocation allowed)
__device__ float g_xh  [N_PAD * H1];       // relu(fc0(x_pad))
__device__ float g_agg [N_PAD * H1];       // mean-aggregated neighbors
__device__ float g_gate[N_PAD * GATES_N];  // pre-activation gates
__device__ int   g_deg [3072];             // in-degree (padded for scan)
__device__ int   g_row [3073];             // CSR row starts
__device__ int   g_cur [N_PAD];            // scatter cursors
__device__ int   g_csr [MAX_E];            // CSR column (src) indices
__device__ int   g_done;                   // last-block ticket for count+scan

// ---------------------------------------------------------------------------
__device__ __forceinline__ unsigned f2tf32(float f) {
    unsigned u;
    asm("cvt.rna.tf32.f32 %0, %1;" : "=r"(u) : "f"(f));
    return u;
}

__device__ __forceinline__ void mma_tf32(float* c, const unsigned* a, const unsigned* b) {
    asm volatile(
        "mma.sync.aligned.m16n8k8.row.col.f32.tf32.tf32.f32 "
        "{%0,%1,%2,%3}, {%4,%5,%6,%7}, {%8,%9}, {%0,%1,%2,%3};\n"
        : "+f"(c[0]), "+f"(c[1]), "+f"(c[2]), "+f"(c[3])
        : "r"(a[0]), "r"(a[1]), "r"(a[2]), "r"(a[3]), "r"(b[0]), "r"(b[1]));
}

// ---------------------------------------------------------------------------
// init: zero counters AND write xh pad rows (rows 2500..2999 of x_pad are
// zero -> xh row = relu(fc0_b)).
__global__ void init_kernel(const float* __restrict__ bias) {
    int i = blockIdx.x * blockDim.x + threadIdx.x;
    if (i == 0)    g_done = 0;
    if (i < 3072)  g_deg[i] = 0;
    if (i < N_PAD) g_cur[i] = 0;
    if (i < (N_PAD - N_REAL) * H1) {
        float v = bias[i & (H1 - 1)];
        g_xh[N_REAL * H1 + i] = v > 0.f ? v : 0.f;
    }
}

// ---------------------------------------------------------------------------
// Shared-memory strides chosen for conflict-free fragment loads:
// As[m][k]: stride 40 -> bank(m*40+k) = 8m+k mod 32, distinct for m in 0..7, k in 0..3
// Bs[k][n]: stride 72 -> bank(k*72+n) = 8k+n mod 32, distinct for k in 0..3, n in 0..7
#define ASTRIDE 40
#define BSTRIDE 72

// GEMM1: xh[m,n] = relu(sum_k x[m,k]*w[n,k] + b[n]), m<2500, n<256, K=1024
// 64x64x32 tile, 128 threads (4 warps of 32x32 warp tiles), tf32 mma.
__global__ void gemm1_kernel(const float* __restrict__ x,
                             const float* __restrict__ w,
                             const float* __restrict__ bias) {
    __shared__ unsigned As[64 * ASTRIDE];
    __shared__ unsigned Bs[32 * BSTRIDE];
    const int bm = blockIdx.y * 64;
    const int bn = blockIdx.x * 64;
    const int tid = threadIdx.x;
    const int warp = tid >> 5, lane = tid & 31;
    const int wm = warp >> 1, wn = warp & 1;
    const int gid = lane >> 2, tig = lane & 3;

    float acc[2][4][4];
#pragma unroll
    for (int mt = 0; mt < 2; mt++)
#pragma unroll
        for (int nt = 0; nt < 4; nt++)
#pragma unroll
            for (int r = 0; r < 4; r++) acc[mt][nt][r] = 0.f;

    const int r0 = tid >> 3;        // 0..15
    const int c8 = tid & 7;         // 0..7 (float4-column)
    const int nb = tid & 63;        // 0..63 (B row = output col)
    const int cb = tid >> 6;        // 0..1

    for (int k0 = 0; k0 < F_IN; k0 += 32) {
#pragma unroll
        for (int rr = 0; rr < 4; rr++) {
            int row = r0 + rr * 16;
            int gm = bm + row;
            float4 v = make_float4(0.f, 0.f, 0.f, 0.f);
            if (gm < N_REAL)
                v = *(const float4*)(x + (size_t)gm * F_IN + k0 + 4 * c8);
            uint4 u = make_uint4(f2tf32(v.x), f2tf32(v.y), f2tf32(v.z), f2tf32(v.w));
            *(uint4*)&As[row * ASTRIDE + 4 * c8] = u;
        }
#pragma unroll
        for (int i = 0; i < 4; i++) {
            int c = cb * 4 + i;   // 0..7
            float4 v = *(const float4*)(w + (size_t)(bn + nb) * F_IN + k0 + 4 * c);
            Bs[(4 * c + 0) * BSTRIDE + nb] = f2tf32(v.x);
            Bs[(4 * c + 1) * BSTRIDE + nb] = f2tf32(v.y);
            Bs[(4 * c + 2) * BSTRIDE + nb] = f2tf32(v.z);
            Bs[(4 * c + 3) * BSTRIDE + nb] = f2tf32(v.w);
        }
        __syncthreads();

#pragma unroll
        for (int ks = 0; ks < 4; ks++) {
            int kk = ks * 8;
            unsigned a[2][4], b[4][2];
#pragma unroll
            for (int mt = 0; mt < 2; mt++) {
                int ar = wm * 32 + mt * 16;
                a[mt][0] = As[(ar + gid) * ASTRIDE + kk + tig];
                a[mt][1] = As[(ar + gid + 8) * ASTRIDE + kk + tig];
                a[mt][2] = As[(ar + gid) * ASTRIDE + kk + tig + 4];
                a[mt][3] = As[(ar + gid + 8) * ASTRIDE + kk + tig + 4];
            }
#pragma unroll
            for (int nt = 0; nt < 4; nt++) {
                int nc = wn * 32 + nt * 8 + gid;
                b[nt][0] = Bs[(kk + tig) * BSTRIDE + nc];
                b[nt][1] = Bs[(kk + tig + 4) * BSTRIDE + nc];
            }
#pragma unroll
            for (int mt = 0; mt < 2; mt++)
#pragma unroll
                for (int nt = 0; nt < 4; nt++)
                    mma_tf32(acc[mt][nt], a[mt], b[nt]);
        }
        __syncthreads();
    }

#pragma unroll
    for (int mt = 0; mt < 2; mt++) {
        int mrow0 = bm + wm * 32 + mt * 16 + gid;
#pragma unroll
        for (int nt = 0; nt < 4; nt++) {
            int ncol = bn + wn * 32 + nt * 8 + 2 * tig;
            float b0 = bias[ncol], b1 = bias[ncol + 1];
            if (mrow0 < N_REAL) {
                float v0 = acc[mt][nt][0] + b0, v1 = acc[mt][nt][1] + b1;
                g_xh[mrow0 * H1 + ncol]     = v0 > 0.f ? v0 : 0.f;
                g_xh[mrow0 * H1 + ncol + 1] = v1 > 0.f ? v1 : 0.f;
            }
            if (mrow0 + 8 < N_REAL) {
                float v2 = acc[mt][nt][2] + b0, v3 = acc[mt][nt][3] + b1;
                g_xh[(mrow0 + 8) * H1 + ncol]     = v2 > 0.f ? v2 : 0.f;
                g_xh[(mrow0 + 8) * H1 + ncol + 1] = v3 > 0.f ? v3 : 0.f;
            }
        }
    }
}

// ---------------------------------------------------------------------------
// count + scan fused.  Per-block smem histogram -> coalesced RED merge; the
// LAST block to finish (ticket) runs the 3072-entry exclusive scan inline,
// removing the dedicated single-block scan launch (~4.6us of pure overhead).
__global__ void count_scan_kernel(const int* __restrict__ ei, int E) {
    __shared__ int hcnt[3008];
    __shared__ int wsum[32];
    __shared__ int slast;
    const int tid = threadIdx.x;

    for (int i = tid; i < 3008; i += blockDim.x) hcnt[i] = 0;
    __syncthreads();

    int q = (E + 3) >> 2;
    int stride = gridDim.x * blockDim.x;
    for (int t = blockIdx.x * blockDim.x + tid; t < q; t += stride) {
        int e = t * 4;
        if (e + 3 < E) {
            int4 d = *(const int4*)(ei + E + e);
            atomicAdd(&hcnt[d.x], 1);
            atomicAdd(&hcnt[d.y], 1);
            atomicAdd(&hcnt[d.z], 1);
            atomicAdd(&hcnt[d.w], 1);
        } else {
            for (int j = e; j < E; j++) atomicAdd(&hcnt[ei[E + j]], 1);
        }
    }
    __syncthreads();
    for (int i = tid; i < 3000; i += blockDim.x) {
        int c = hcnt[i];
        if (c) atomicAdd(&g_deg[i], c);
    }

    // Ticket: last block performs the scan.
    __threadfence();
    if (tid == 0) {
        int ticket = atomicAdd(&g_done, 1);
        slast = (ticket == gridDim.x - 1);
    }
    __syncthreads();
    if (!slast) return;
    __threadfence();

    // Exclusive scan over 3072 degrees: 1024 threads, 3 elems each.
    const int lane = tid & 31, wid = tid >> 5;
    int base = tid * 3;
    int v0 = g_deg[base], v1 = g_deg[base + 1], v2 = g_deg[base + 2];
    int s = v0 + v1 + v2;
    int inc = s;
#pragma unroll
    for (int o = 1; o < 32; o <<= 1) {
        int n = __shfl_up_sync(0xffffffffu, inc, o);
        if (lane >= o) inc += n;
    }
    if (lane == 31) wsum[wid] = inc;
    __syncthreads();
    if (wid == 0) {
        int w = wsum[lane];
#pragma unroll
        for (int o = 1; o < 32; o <<= 1) {
            int n = __shfl_up_sync(0xffffffffu, w, o);
            if (lane >= o) w += n;
        }
        wsum[lane] = w;
    }
    __syncthreads();
    int excl = inc - s + (wid > 0 ? wsum[wid - 1] : 0);
    g_row[base + 0] = excl;
    g_row[base + 1] = excl + v0;
    g_row[base + 2] = excl + v0 + v1;
    if (tid == 1023) g_row[3072] = excl + s;
}

// ---------------------------------------------------------------------------
// Scatter with per-block range reservation: histogram chunk in smem, ONE
// global atomic per distinct dst per block (spread addresses), then place
// edges via cheap smem cursors.  ~3x fewer global atomics, less per-address
// serialization than the naive per-edge atomicAdd.
__global__ void scatter_kernel(const int* __restrict__ ei, int E) {
    __shared__ int hcnt[3000];
    __shared__ int hbase[3000];
    const int tid = threadIdx.x;
    const int CH = (E + gridDim.x - 1) / gridDim.x;
    const int lo = blockIdx.x * CH;
    const int hi = min(E, lo + CH);

    for (int i = tid; i < 3000; i += blockDim.x) hcnt[i] = 0;
    __syncthreads();
    for (int e = lo + tid; e < hi; e += blockDim.x)
        atomicAdd(&hcnt[ei[E + e]], 1);
    __syncthreads();
    for (int i = tid; i < 3000; i += blockDim.x) {
        int c = hcnt[i];
        if (c) hbase[i] = g_row[i] + atomicAdd(&g_cur[i], c);
        hcnt[i] = 0;
    }
    __syncthreads();
    for (int e = lo + tid; e < hi; e += blockDim.x) {
        int d = ei[E + e];
        int p = atomicAdd(&hcnt[d], 1);
        g_csr[hbase[d] + p] = ei[e];
    }
}

// ---------------------------------------------------------------------------
// Gather: one 64-thread block per dst node; thread t owns float4 features
// [4t, 4t+4).  4-edge unroll -> 4 outstanding LDG.128 per thread.
__global__ void gather_kernel() {
    const int n = blockIdx.x;
    const int t = threadIdx.x;        // 0..63
    const int start = g_row[n];
    const int deg = g_row[n + 1] - start;

    __shared__ int ssrc[64];
    float4 acc = make_float4(0.f, 0.f, 0.f, 0.f);
    for (int j0 = 0; j0 < deg; j0 += 64) {
        int m = min(64, deg - j0);
        if (t < m) ssrc[t] = g_csr[start + j0 + t];
        __syncthreads();
        int j = 0;
        for (; j + 4 <= m; j += 4) {
            const float4 a0 = *(const float4*)(g_xh + ssrc[j]     * H1 + 4 * t);
            const float4 a1 = *(const float4*)(g_xh + ssrc[j + 1] * H1 + 4 * t);
            const float4 a2 = *(const float4*)(g_xh + ssrc[j + 2] * H1 + 4 * t);
            const float4 a3 = *(const float4*)(g_xh + ssrc[j + 3] * H1 + 4 * t);
            acc.x += (a0.x + a1.x) + (a2.x + a3.x);
            acc.y += (a0.y + a1.y) + (a2.y + a3.y);
            acc.z += (a0.z + a1.z) + (a2.z + a3.z);
            acc.w += (a0.w + a1.w) + (a2.w + a3.w);
        }
        for (; j < m; j++) {
            const float4 a = *(const float4*)(g_xh + ssrc[j] * H1 + 4 * t);
            acc.x += a.x; acc.y += a.y; acc.z += a.z; acc.w += a.w;
        }
        __syncthreads();
    }
    float inv = 1.f / fmaxf((float)deg, 1.f);
    acc.x *= inv; acc.y *= inv; acc.z *= inv; acc.w *= inv;
    *(float4*)(g_agg + n * H1 + 4 * t) = acc;
}

// ---------------------------------------------------------------------------
// GEMM2 (tf32): gate[m, j] = sum_k A[m,k]*B[k,j] + bx[j] + bh[j]
//   A[m,k] = (k<256) ? agg[m,k] : xh[m,k-256]   (M=3000, K=512)
//   B[k,j], j = gate*128+o: (k<256) ? Wx_rel[gate,k,o] : Wx_root[gate,k-256,o]
__global__ void gemm2_kernel(const float* __restrict__ Wrel,
                             const float* __restrict__ Wroot,
                             const float* __restrict__ bx,
                             const float* __restrict__ bh) {
    __shared__ unsigned As[64 * ASTRIDE];
    __shared__ unsigned Bs[32 * BSTRIDE];
    const int bm = blockIdx.y * 64;
    const int bn = blockIdx.x * 64;
    const int tid = threadIdx.x;
    const int warp = tid >> 5, lane = tid & 31;
    const int wm = warp >> 1, wn = warp & 1;
    const int gid = lane >> 2, tig = lane & 3;
    const int gate = bn >> 7;
    const int obase = bn & 127;

    float acc[2][4][4];
#pragma unroll
    for (int mt = 0; mt < 2; mt++)
#pragma unroll
        for (int nt = 0; nt < 4; nt++)
#pragma unroll
            for (int r = 0; r < 4; r++) acc[mt][nt][r] = 0.f;

    const int r0 = tid >> 3;
    const int c8 = tid & 7;
    const int ob = tid & 63;
    const int kc = tid >> 6;     // 0..1

    for (int k0 = 0; k0 < 2 * H1; k0 += 32) {
        const float* Abase = (k0 < H1) ? (g_agg + k0) : (g_xh + (k0 - H1));
#pragma unroll
        for (int rr = 0; rr < 4; rr++) {
            int row = r0 + rr * 16;
            int gm = bm + row;
            float4 v = make_float4(0.f, 0.f, 0.f, 0.f);
            if (gm < N_PAD)
                v = *(const float4*)(Abase + (size_t)gm * H1 + 4 * c8);
            uint4 u = make_uint4(f2tf32(v.x), f2tf32(v.y), f2tf32(v.z), f2tf32(v.w));
            *(uint4*)&As[row * ASTRIDE + 4 * c8] = u;
        }
        const float* Wbase = (k0 < H1)
            ? (Wrel  + (size_t)gate * H1 * OUTD + (size_t)k0 * OUTD + obase)
            : (Wroot + (size_t)gate * H1 * OUTD + (size_t)(k0 - H1) * OUTD + obase);
#pragma unroll
        for (int i = 0; i < 16; i++) {
            int k = kc * 16 + i;
            Bs[k * BSTRIDE + ob] = f2tf32(Wbase[(size_t)k * OUTD + ob]);
        }
        __syncthreads();

#pragma unroll
        for (int ks = 0; ks < 4; ks++) {
            int kk = ks * 8;
            unsigned a[2][4], b[4][2];
#pragma unroll
            for (int mt = 0; mt < 2; mt++) {
                int ar = wm * 32 + mt * 16;
                a[mt][0] = As[(ar + gid) * ASTRIDE + kk + tig];
                a[mt][1] = As[(ar + gid + 8) * ASTRIDE + kk + tig];
                a[mt][2] = As[(ar + gid) * ASTRIDE + kk + tig + 4];
                a[mt][3] = As[(ar + gid + 8) * ASTRIDE + kk + tig + 4];
            }
#pragma unroll
            for (int nt = 0; nt < 4; nt++) {
                int nc = wn * 32 + nt * 8 + gid;
                b[nt][0] = Bs[(kk + tig) * BSTRIDE + nc];
                b[nt][1] = Bs[(kk + tig + 4) * BSTRIDE + nc];
            }
#pragma unroll
            for (int mt = 0; mt < 2; mt++)
#pragma unroll
                for (int nt = 0; nt < 4; nt++)
                    mma_tf32(acc[mt][nt], a[mt], b[nt]);
        }
        __syncthreads();
    }

#pragma unroll
    for (int mt = 0; mt < 2; mt++) {
        int mrow0 = bm + wm * 32 + mt * 16 + gid;
#pragma unroll
        for (int nt = 0; nt < 4; nt++) {
            int ncol = bn + wn * 32 + nt * 8 + 2 * tig;      // global gate col
            float b0 = bx[ncol] + bh[ncol];
            float b1 = bx[ncol + 1] + bh[ncol + 1];
            if (mrow0 < N_PAD) {
                g_gate[(size_t)mrow0 * GATES_N + ncol]     = acc[mt][nt][0] + b0;
                g_gate[(size_t)mrow0 * GATES_N + ncol + 1] = acc[mt][nt][1] + b1;
            }
            if (mrow0 + 8 < N_PAD) {
                g_gate[(size_t)(mrow0 + 8) * GATES_N + ncol]     = acc[mt][nt][2] + b0;
                g_gate[(size_t)(mrow0 + 8) * GATES_N + ncol + 1] = acc[mt][nt][3] + b1;
            }
        }
    }
}

// ---------------------------------------------------------------------------
// Gates + H + final projection. C_prev = 0 so forget gate is dead.
__global__ void finish_kernel(const float* __restrict__ fcw,
                              const float* __restrict__ fcb,
                              float* __restrict__ out,
                              float* __restrict__ Hout) {
    int n = blockIdx.x;       // 0..2999
    int o = threadIdx.x;      // 0..127
    const float* g = g_gate + (size_t)n * GATES_N;
    float gi = g[o];
    float gc = g[2 * OUTD + o];
    float go = g[3 * OUTD + o];
    float I = 1.f / (1.f + __expf(-gi));
    float T = tanhf(gc);
    float O = 1.f / (1.f + __expf(-go));
    float C = I * T;
    float H = O * tanhf(C);
    Hout[n * OUTD + o] = H;

    float v = H * fcw[o];
#pragma unroll
    for (int s = 16; s > 0; s >>= 1)
        v += __shfl_down_sync(0xffffffffu, v, s);
    __shared__ float sred[4];
    if ((o & 31) == 0) sred[o >> 5] = v;
    __syncthreads();
    if (o == 0 && n < N_REAL)
        out[n] = sred[0] + sred[1] + sred[2] + sred[3] + fcb[0];
}

// ---------------------------------------------------------------------------
extern "C" void kernel_launch(void* const* d_in, const int* in_sizes, int n_in,
                              void* d_out, int out_size) {
    const float* x      = (const float*)d_in[0];
    const int*   ei     = (const int*)  d_in[1];
    const float* fc0_w  = (const float*)d_in[2];
    const float* fc0_b  = (const float*)d_in[3];
    const float* Wx_rel = (const float*)d_in[4];
    const float* Wx_root= (const float*)d_in[5];
    const float* bx     = (const float*)d_in[6];
    // d_in[7] Wh_rel, d_in[8] Wh_root: multiplied by zero state -> unused
    const float* bh     = (const float*)d_in[9];
    const float* fc_w   = (const float*)d_in[10];
    const float* fc_b   = (const float*)d_in[11];
    const int E = in_sizes[1] / 2;

    float* out  = (float*)d_out;          // [2500]
    float* Hout = out + N_REAL;           // [3000 x 128]

    init_kernel<<<((N_PAD - N_REAL) * H1 + 255) / 256, 256>>>(fc0_b);

    dim3 g1(H1 / 64, (N_REAL + 63) / 64);          // 4 x 40
    gemm1_kernel<<<g1, 128>>>(x, fc0_w, fc0_b);

    count_scan_kernel<<<CNT_BLOCKS, 1024>>>(ei, E);
    scatter_kernel<<<SCT_BLOCKS, 1024>>>(ei, E);
    gather_kernel<<<N_PAD, 64>>>();

    dim3 g2(GATES_N / 64, (N_PAD + 63) / 64);      // 8 x 47
    gemm2_kernel<<<g2, 128>>>(Wx_rel, Wx_root, bx, bh);

    finish_kernel<<<N_PAD, OUTD>>>(fc_w, fc_b, out, Hout);
}

// round 8
// speedup vs baseline: 1.7168x; 1.0409x over previous
#include <cuda_runtime.h>

#define N_PAD   3000
#define N_REAL  2500
#define F_IN    1024
#define H1      256
#define OUTD    128
#define GATES_N 512   // 4 gates x 128
#define MAX_E   1048576
#define CSR_BLOCKS 128   // <= SM count: all blocks resident in wave 1 (spin-safe)

// Scratch (device globals — no allocation allowed)
__device__ float g_xh  [N_PAD * H1];       // relu(fc0(x_pad))
__device__ float g_agg [N_PAD * H1];       // mean-aggregated neighbors
__device__ float g_gate[N_PAD * GATES_N];  // pre-activation gates
__device__ int   g_deg [3072];             // in-degree (padded for scan)
__device__ int   g_row [3073];             // CSR row starts
__device__ int   g_cur [N_PAD];            // reservation cursors
__device__ int   g_csr [MAX_E];            // CSR column (src) indices
__device__ int   g_done;                   // count-phase ticket
__device__ int   g_flag;                   // scan-complete flag

// ---------------------------------------------------------------------------
__device__ __forceinline__ unsigned f2tf32(float f) {
    unsigned u;
    asm("cvt.rna.tf32.f32 %0, %1;" : "=r"(u) : "f"(f));
    return u;
}

__device__ __forceinline__ void mma_tf32(float* c, const unsigned* a, const unsigned* b) {
    asm volatile(
        "mma.sync.aligned.m16n8k8.row.col.f32.tf32.tf32.f32 "
        "{%0,%1,%2,%3}, {%4,%5,%6,%7}, {%8,%9}, {%0,%1,%2,%3};\n"
        : "+f"(c[0]), "+f"(c[1]), "+f"(c[2]), "+f"(c[3])
        : "r"(a[0]), "r"(a[1]), "r"(a[2]), "r"(a[3]), "r"(b[0]), "r"(b[1]));
}

// ---------------------------------------------------------------------------
// init: zero counters/flags AND write xh pad rows (rows 2500..2999 of x_pad
// are zero -> xh row = relu(fc0_b)).
__global__ void init_kernel(const float* __restrict__ bias) {
    int i = blockIdx.x * blockDim.x + threadIdx.x;
    if (i == 0)    { g_done = 0; g_flag = 0; }
    if (i < 3072)  g_deg[i] = 0;
    if (i < N_PAD) g_cur[i] = 0;
    if (i < (N_PAD - N_REAL) * H1) {
        float v = bias[i & (H1 - 1)];
        g_xh[N_REAL * H1 + i] = v > 0.f ? v : 0.f;
    }
}

// ---------------------------------------------------------------------------
// Shared-memory strides chosen for conflict-free fragment loads:
// As[m][k]: stride 40 -> bank(m*40+k) = 8m+k mod 32, distinct for m in 0..7, k in 0..3
// Bs[k][n]: stride 72 -> bank(k*72+n) = 8k+n mod 32, distinct for k in 0..3, n in 0..7
#define ASTRIDE 40
#define BSTRIDE 72

// GEMM1: xh[m,n] = relu(sum_k x[m,k]*w[n,k] + b[n]), m<2500, n<256, K=1024
// 64x64x32 tile, 128 threads (4 warps of 32x32 warp tiles), tf32 mma.
__global__ void gemm1_kernel(const float* __restrict__ x,
                             const float* __restrict__ w,
                             const float* __restrict__ bias) {
    __shared__ unsigned As[64 * ASTRIDE];
    __shared__ unsigned Bs[32 * BSTRIDE];
    const int bm = blockIdx.y * 64;
    const int bn = blockIdx.x * 64;
    const int tid = threadIdx.x;
    const int warp = tid >> 5, lane = tid & 31;
    const int wm = warp >> 1, wn = warp & 1;
    const int gid = lane >> 2, tig = lane & 3;

    float acc[2][4][4];
#pragma unroll
    for (int mt = 0; mt < 2; mt++)
#pragma unroll
        for (int nt = 0; nt < 4; nt++)
#pragma unroll
            for (int r = 0; r < 4; r++) acc[mt][nt][r] = 0.f;

    const int r0 = tid >> 3;        // 0..15
    const int c8 = tid & 7;         // 0..7 (float4-column)
    const int nb = tid & 63;        // 0..63 (B row = output col)
    const int cb = tid >> 6;        // 0..1

    for (int k0 = 0; k0 < F_IN; k0 += 32) {
#pragma unroll
        for (int rr = 0; rr < 4; rr++) {
            int row = r0 + rr * 16;
            int gm = bm + row;
            float4 v = make_float4(0.f, 0.f, 0.f, 0.f);
            if (gm < N_REAL)
                v = *(const float4*)(x + (size_t)gm * F_IN + k0 + 4 * c8);
            uint4 u = make_uint4(f2tf32(v.x), f2tf32(v.y), f2tf32(v.z), f2tf32(v.w));
            *(uint4*)&As[row * ASTRIDE + 4 * c8] = u;
        }
#pragma unroll
        for (int i = 0; i < 4; i++) {
            int c = cb * 4 + i;   // 0..7
            float4 v = *(const float4*)(w + (size_t)(bn + nb) * F_IN + k0 + 4 * c);
            Bs[(4 * c + 0) * BSTRIDE + nb] = f2tf32(v.x);
            Bs[(4 * c + 1) * BSTRIDE + nb] = f2tf32(v.y);
            Bs[(4 * c + 2) * BSTRIDE + nb] = f2tf32(v.z);
            Bs[(4 * c + 3) * BSTRIDE + nb] = f2tf32(v.w);
        }
        __syncthreads();

#pragma unroll
        for (int ks = 0; ks < 4; ks++) {
            int kk = ks * 8;
            unsigned a[2][4], b[4][2];
#pragma unroll
            for (int mt = 0; mt < 2; mt++) {
                int ar = wm * 32 + mt * 16;
                a[mt][0] = As[(ar + gid) * ASTRIDE + kk + tig];
                a[mt][1] = As[(ar + gid + 8) * ASTRIDE + kk + tig];
                a[mt][2] = As[(ar + gid) * ASTRIDE + kk + tig + 4];
                a[mt][3] = As[(ar + gid + 8) * ASTRIDE + kk + tig + 4];
            }
#pragma unroll
            for (int nt = 0; nt < 4; nt++) {
                int nc = wn * 32 + nt * 8 + gid;
                b[nt][0] = Bs[(kk + tig) * BSTRIDE + nc];
                b[nt][1] = Bs[(kk + tig + 4) * BSTRIDE + nc];
            }
#pragma unroll
            for (int mt = 0; mt < 2; mt++)
#pragma unroll
                for (int nt = 0; nt < 4; nt++)
                    mma_tf32(acc[mt][nt], a[mt], b[nt]);
        }
        __syncthreads();
    }

#pragma unroll
    for (int mt = 0; mt < 2; mt++) {
        int mrow0 = bm + wm * 32 + mt * 16 + gid;
#pragma unroll
        for (int nt = 0; nt < 4; nt++) {
            int ncol = bn + wn * 32 + nt * 8 + 2 * tig;
            float b0 = bias[ncol], b1 = bias[ncol + 1];
            if (mrow0 < N_REAL) {
                float v0 = acc[mt][nt][0] + b0, v1 = acc[mt][nt][1] + b1;
                g_xh[mrow0 * H1 + ncol]     = v0 > 0.f ? v0 : 0.f;
                g_xh[mrow0 * H1 + ncol + 1] = v1 > 0.f ? v1 : 0.f;
            }
            if (mrow0 + 8 < N_REAL) {
                float v2 = acc[mt][nt][2] + b0, v3 = acc[mt][nt][3] + b1;
                g_xh[(mrow0 + 8) * H1 + ncol]     = v2 > 0.f ? v2 : 0.f;
                g_xh[(mrow0 + 8) * H1 + ncol + 1] = v3 > 0.f ? v3 : 0.f;
            }
        }
    }
}

// ---------------------------------------------------------------------------
// Fused CSR build: count -> (ticketed) scan -> reserve -> place, one kernel.
// All CSR_BLOCKS are resident simultaneously (grid <= SM count), so the
// flag spin cannot deadlock.  Each block's smem histogram from the count
// phase is REUSED for the reservation phase (no second histogram pass).
__global__ void __launch_bounds__(1024, 1) csr_kernel(const int* __restrict__ ei, int E) {
    __shared__ int hcnt [3000];
    __shared__ int hbase[3000];
    __shared__ int wsum[32];
    __shared__ int slast;
    const int tid = threadIdx.x;
    const int CH = (E + gridDim.x - 1) / gridDim.x;
    const int lo = blockIdx.x * CH;
    const int hi = min(E, lo + CH);

    // ---- phase 1: per-block histogram + merge to global degrees
    for (int i = tid; i < 3000; i += blockDim.x) hcnt[i] = 0;
    __syncthreads();
    for (int e = lo + tid; e < hi; e += blockDim.x)
        atomicAdd(&hcnt[ei[E + e]], 1);
    __syncthreads();
    for (int i = tid; i < 3000; i += blockDim.x) {
        int c = hcnt[i];
        if (c) atomicAdd(&g_deg[i], c);
    }
    __threadfence();
    if (tid == 0) {
        int t = atomicAdd(&g_done, 1);
        slast = (t == (int)gridDim.x - 1);
    }
    __syncthreads();

    // ---- phase 2: last block scans; others wait on flag
    if (slast) {
        __threadfence();
        const int lane = tid & 31, wid = tid >> 5;
        int base = tid * 3;
        int v0 = g_deg[base], v1 = g_deg[base + 1], v2 = g_deg[base + 2];
        int s = v0 + v1 + v2;
        int inc = s;
#pragma unroll
        for (int o = 1; o < 32; o <<= 1) {
            int n = __shfl_up_sync(0xffffffffu, inc, o);
            if (lane >= o) inc += n;
        }
        if (lane == 31) wsum[wid] = inc;
        __syncthreads();
        if (wid == 0) {
            int w = wsum[lane];
#pragma unroll
            for (int o = 1; o < 32; o <<= 1) {
                int n = __shfl_up_sync(0xffffffffu, w, o);
                if (lane >= o) w += n;
            }
            wsum[lane] = w;
        }
        __syncthreads();
        int excl = inc - s + (wid > 0 ? wsum[wid - 1] : 0);
        g_row[base + 0] = excl;
        g_row[base + 1] = excl + v0;
        g_row[base + 2] = excl + v0 + v1;
        if (tid == 1023) g_row[3072] = excl + s;
        __threadfence();
        __syncthreads();
        if (tid == 0) atomicExch(&g_flag, 1);
    } else {
        if (tid == 0) {
            while (atomicAdd(&g_flag, 0) == 0) __nanosleep(128);
        }
    }
    __syncthreads();
    __threadfence();

    // ---- phase 3: reserve contiguous ranges (one spread atomic per distinct
    //               dst per block), reusing the phase-1 histogram.
    for (int i = tid; i < 3000; i += blockDim.x) {
        int c = hcnt[i];
        if (c) hbase[i] = g_row[i] + atomicAdd(&g_cur[i], c);
        hcnt[i] = 0;
    }
    __syncthreads();

    // ---- phase 4: place edges via cheap smem cursors
    for (int e = lo + tid; e < hi; e += blockDim.x) {
        int d = ei[E + e];
        int p = atomicAdd(&hcnt[d], 1);
        g_csr[hbase[d] + p] = ei[e];
    }
}

// ---------------------------------------------------------------------------
// Gather: one 64-thread block per dst node; thread t owns float4 features
// [4t, 4t+4).  4-edge unroll -> 4 outstanding LDG.128 per thread.
__global__ void gather_kernel() {
    const int n = blockIdx.x;
    const int t = threadIdx.x;        // 0..63
    const int start = g_row[n];
    const int deg = g_row[n + 1] - start;

    __shared__ int ssrc[64];
    float4 acc = make_float4(0.f, 0.f, 0.f, 0.f);
    for (int j0 = 0; j0 < deg; j0 += 64) {
        int m = min(64, deg - j0);
        if (t < m) ssrc[t] = g_csr[start + j0 + t];
        __syncthreads();
        int j = 0;
        for (; j + 4 <= m; j += 4) {
            const float4 a0 = *(const float4*)(g_xh + ssrc[j]     * H1 + 4 * t);
            const float4 a1 = *(const float4*)(g_xh + ssrc[j + 1] * H1 + 4 * t);
            const float4 a2 = *(const float4*)(g_xh + ssrc[j + 2] * H1 + 4 * t);
            const float4 a3 = *(const float4*)(g_xh + ssrc[j + 3] * H1 + 4 * t);
            acc.x += (a0.x + a1.x) + (a2.x + a3.x);
            acc.y += (a0.y + a1.y) + (a2.y + a3.y);
            acc.z += (a0.z + a1.z) + (a2.z + a3.z);
            acc.w += (a0.w + a1.w) + (a2.w + a3.w);
        }
        for (; j < m; j++) {
            const float4 a = *(const float4*)(g_xh + ssrc[j] * H1 + 4 * t);
            acc.x += a.x; acc.y += a.y; acc.z += a.z; acc.w += a.w;
        }
        __syncthreads();
    }
    float inv = 1.f / fmaxf((float)deg, 1.f);
    acc.x *= inv; acc.y *= inv; acc.z *= inv; acc.w *= inv;
    *(float4*)(g_agg + n * H1 + 4 * t) = acc;
}

// ---------------------------------------------------------------------------
// GEMM2 (tf32): gate[m, j] = sum_k A[m,k]*B[k,j] + bx[j] + bh[j]
//   A[m,k] = (k<256) ? agg[m,k] : xh[m,k-256]   (M=3000, K=512)
//   B[k,j], j = gate*128+o: (k<256) ? Wx_rel[gate,k,o] : Wx_root[gate,k-256,o]
__global__ void gemm2_kernel(const float* __restrict__ Wrel,
                             const float* __restrict__ Wroot,
                             const float* __restrict__ bx,
                             const float* __restrict__ bh) {
    __shared__ unsigned As[64 * ASTRIDE];
    __shared__ unsigned Bs[32 * BSTRIDE];
    const int bm = blockIdx.y * 64;
    const int bn = blockIdx.x * 64;
    const int tid = threadIdx.x;
    const int warp = tid >> 5, lane = tid & 31;
    const int wm = warp >> 1, wn = warp & 1;
    const int gid = lane >> 2, tig = lane & 3;
    const int gate = bn >> 7;
    const int obase = bn & 127;

    float acc[2][4][4];
#pragma unroll
    for (int mt = 0; mt < 2; mt++)
#pragma unroll
        for (int nt = 0; nt < 4; nt++)
#pragma unroll
            for (int r = 0; r < 4; r++) acc[mt][nt][r] = 0.f;

    const int r0 = tid >> 3;
    const int c8 = tid & 7;
    const int ob = tid & 63;
    const int kc = tid >> 6;     // 0..1

    for (int k0 = 0; k0 < 2 * H1; k0 += 32) {
        const float* Abase = (k0 < H1) ? (g_agg + k0) : (g_xh + (k0 - H1));
#pragma unroll
        for (int rr = 0; rr < 4; rr++) {
            int row = r0 + rr * 16;
            int gm = bm + row;
            float4 v = make_float4(0.f, 0.f, 0.f, 0.f);
            if (gm < N_PAD)
                v = *(const float4*)(Abase + (size_t)gm * H1 + 4 * c8);
            uint4 u = make_uint4(f2tf32(v.x), f2tf32(v.y), f2tf32(v.z), f2tf32(v.w));
            *(uint4*)&As[row * ASTRIDE + 4 * c8] = u;
        }
        const float* Wbase = (k0 < H1)
            ? (Wrel  + (size_t)gate * H1 * OUTD + (size_t)k0 * OUTD + obase)
            : (Wroot + (size_t)gate * H1 * OUTD + (size_t)(k0 - H1) * OUTD + obase);
#pragma unroll
        for (int i = 0; i < 16; i++) {
            int k = kc * 16 + i;
            Bs[k * BSTRIDE + ob] = f2tf32(Wbase[(size_t)k * OUTD + ob]);
        }
        __syncthreads();

#pragma unroll
        for (int ks = 0; ks < 4; ks++) {
            int kk = ks * 8;
            unsigned a[2][4], b[4][2];
#pragma unroll
            for (int mt = 0; mt < 2; mt++) {
                int ar = wm * 32 + mt * 16;
                a[mt][0] = As[(ar + gid) * ASTRIDE + kk + tig];
                a[mt][1] = As[(ar + gid + 8) * ASTRIDE + kk + tig];
                a[mt][2] = As[(ar + gid) * ASTRIDE + kk + tig + 4];
                a[mt][3] = As[(ar + gid + 8) * ASTRIDE + kk + tig + 4];
            }
#pragma unroll
            for (int nt = 0; nt < 4; nt++) {
                int nc = wn * 32 + nt * 8 + gid;
                b[nt][0] = Bs[(kk + tig) * BSTRIDE + nc];
                b[nt][1] = Bs[(kk + tig + 4) * BSTRIDE + nc];
            }
#pragma unroll
            for (int mt = 0; mt < 2; mt++)
#pragma unroll
                for (int nt = 0; nt < 4; nt++)
                    mma_tf32(acc[mt][nt], a[mt], b[nt]);
        }
        __syncthreads();
    }

#pragma unroll
    for (int mt = 0; mt < 2; mt++) {
        int mrow0 = bm + wm * 32 + mt * 16 + gid;
#pragma unroll
        for (int nt = 0; nt < 4; nt++) {
            int ncol = bn + wn * 32 + nt * 8 + 2 * tig;      // global gate col
            float b0 = bx[ncol] + bh[ncol];
            float b1 = bx[ncol + 1] + bh[ncol + 1];
            if (mrow0 < N_PAD) {
                g_gate[(size_t)mrow0 * GATES_N + ncol]     = acc[mt][nt][0] + b0;
                g_gate[(size_t)mrow0 * GATES_N + ncol + 1] = acc[mt][nt][1] + b1;
            }
            if (mrow0 + 8 < N_PAD) {
                g_gate[(size_t)(mrow0 + 8) * GATES_N + ncol]     = acc[mt][nt][2] + b0;
                g_gate[(size_t)(mrow0 + 8) * GATES_N + ncol + 1] = acc[mt][nt][3] + b1;
            }
        }
    }
}

// ---------------------------------------------------------------------------
// Gates + H + final projection. C_prev = 0 so forget gate is dead.
__global__ void finish_kernel(const float* __restrict__ fcw,
                              const float* __restrict__ fcb,
                              float* __restrict__ out,
                              float* __restrict__ Hout) {
    int n = blockIdx.x;       // 0..2999
    int o = threadIdx.x;      // 0..127
    const float* g = g_gate + (size_t)n * GATES_N;
    float gi = g[o];
    float gc = g[2 * OUTD + o];
    float go = g[3 * OUTD + o];
    float I = 1.f / (1.f + __expf(-gi));
    float T = tanhf(gc);
    float O = 1.f / (1.f + __expf(-go));
    float C = I * T;
    float H = O * tanhf(C);
    Hout[n * OUTD + o] = H;

    float v = H * fcw[o];
#pragma unroll
    for (int s = 16; s > 0; s >>= 1)
        v += __shfl_down_sync(0xffffffffu, v, s);
    __shared__ float sred[4];
    if ((o & 31) == 0) sred[o >> 5] = v;
    __syncthreads();
    if (o == 0 && n < N_REAL)
        out[n] = sred[0] + sred[1] + sred[2] + sred[3] + fcb[0];
}

// ---------------------------------------------------------------------------
extern "C" void kernel_launch(void* const* d_in, const int* in_sizes, int n_in,
                              void* d_out, int out_size) {
    const float* x      = (const float*)d_in[0];
    const int*   ei     = (const int*)  d_in[1];
    const float* fc0_w  = (const float*)d_in[2];
    const float* fc0_b  = (const float*)d_in[3];
    const float* Wx_rel = (const float*)d_in[4];
    const float* Wx_root= (const float*)d_in[5];
    const float* bx     = (const float*)d_in[6];
    // d_in[7] Wh_rel, d_in[8] Wh_root: multiplied by zero state -> unused
    const float* bh     = (const float*)d_in[9];
    const float* fc_w   = (const float*)d_in[10];
    const float* fc_b   = (const float*)d_in[11];
    const int E = in_sizes[1] / 2;

    float* out  = (float*)d_out;          // [2500]
    float* Hout = out + N_REAL;           // [3000 x 128]

    init_kernel<<<((N_PAD - N_REAL) * H1 + 255) / 256, 256>>>(fc0_b);

    dim3 g1(H1 / 64, (N_REAL + 63) / 64);          // 4 x 40
    gemm1_kernel<<<g1, 128>>>(x, fc0_w, fc0_b);

    csr_kernel<<<CSR_BLOCKS, 1024>>>(ei, E);
    gather_kernel<<<N_PAD, 64>>>();

    dim3 g2(GATES_N / 64, (N_PAD + 63) / 64);      // 8 x 47
    gemm2_kernel<<<g2, 128>>>(Wx_rel, Wx_root, bx, bh);

    finish_kernel<<<N_PAD, OUTD>>>(fc_w, fc_b, out, Hout);
}

// round 9
// speedup vs baseline: 1.7958x; 1.0460x over previous
#include <cuda_runtime.h>

#define N_PAD   3000
#define N_REAL  2500
#define F_IN    1024
#define H1      256
#define OUTD    128
#define GATES_N 512   // 4 gates x 128
#define MAX_E   1048576
#define SLOT    256      // per-node CSR capacity (max degree ~137, 15-sigma safe)
#define CSR_BLOCKS 128

// Scratch (device globals — no allocation allowed)
__device__ float g_xh  [N_PAD * H1];       // relu(fc0(x_pad))
__device__ float g_agg [N_PAD * H1];       // mean-aggregated neighbors
__device__ float g_gate[N_PAD * GATES_N];  // pre-activation gates
__device__ int   g_cur [N_PAD];            // per-node fill cursor == degree
__device__ int   g_csr [N_PAD * SLOT];     // slotted CSR (stride 256 per node)

// ---------------------------------------------------------------------------
__device__ __forceinline__ unsigned f2tf32(float f) {
    unsigned u;
    asm("cvt.rna.tf32.f32 %0, %1;" : "=r"(u) : "f"(f));
    return u;
}

__device__ __forceinline__ void mma_tf32(float* c, const unsigned* a, const unsigned* b) {
    asm volatile(
        "mma.sync.aligned.m16n8k8.row.col.f32.tf32.tf32.f32 "
        "{%0,%1,%2,%3}, {%4,%5,%6,%7}, {%8,%9}, {%0,%1,%2,%3};\n"
        : "+f"(c[0]), "+f"(c[1]), "+f"(c[2]), "+f"(c[3])
        : "r"(a[0]), "r"(a[1]), "r"(a[2]), "r"(a[3]), "r"(b[0]), "r"(b[1]));
}

// ---------------------------------------------------------------------------
// init: zero cursors AND write xh pad rows (rows 2500..2999 of x_pad are
// zero -> xh row = relu(fc0_b)).
__global__ void init_kernel(const float* __restrict__ bias) {
    int i = blockIdx.x * blockDim.x + threadIdx.x;
    if (i < N_PAD) g_cur[i] = 0;
    if (i < (N_PAD - N_REAL) * H1) {
        float v = bias[i & (H1 - 1)];
        g_xh[N_REAL * H1 + i] = v > 0.f ? v : 0.f;
    }
}

// ---------------------------------------------------------------------------
// Shared-memory strides chosen for conflict-free fragment loads:
// As[m][k]: stride 40 -> bank(m*40+k) = 8m+k mod 32, distinct for m in 0..7, k in 0..3
// Bs[k][n]: stride 72 -> bank(k*72+n) = 8k+n mod 32, distinct for k in 0..3, n in 0..7
#define ASTRIDE 40
#define BSTRIDE 72

// GEMM1: xh[m,n] = relu(sum_k x[m,k]*w[n,k] + b[n]), m<2500, n<256, K=1024
// 64x64x32 tile, 128 threads (4 warps of 32x32 warp tiles), tf32 mma.
__global__ void gemm1_kernel(const float* __restrict__ x,
                             const float* __restrict__ w,
                             const float* __restrict__ bias) {
    __shared__ unsigned As[64 * ASTRIDE];
    __shared__ unsigned Bs[32 * BSTRIDE];
    const int bm = blockIdx.y * 64;
    const int bn = blockIdx.x * 64;
    const int tid = threadIdx.x;
    const int warp = tid >> 5, lane = tid & 31;
    const int wm = warp >> 1, wn = warp & 1;
    const int gid = lane >> 2, tig = lane & 3;

    float acc[2][4][4];
#pragma unroll
    for (int mt = 0; mt < 2; mt++)
#pragma unroll
        for (int nt = 0; nt < 4; nt++)
#pragma unroll
            for (int r = 0; r < 4; r++) acc[mt][nt][r] = 0.f;

    const int r0 = tid >> 3;        // 0..15
    const int c8 = tid & 7;         // 0..7 (float4-column)
    const int nb = tid & 63;        // 0..63 (B row = output col)
    const int cb = tid >> 6;        // 0..1

    for (int k0 = 0; k0 < F_IN; k0 += 32) {
#pragma unroll
        for (int rr = 0; rr < 4; rr++) {
            int row = r0 + rr * 16;
            int gm = bm + row;
            float4 v = make_float4(0.f, 0.f, 0.f, 0.f);
            if (gm < N_REAL)
                v = *(const float4*)(x + (size_t)gm * F_IN + k0 + 4 * c8);
            uint4 u = make_uint4(f2tf32(v.x), f2tf32(v.y), f2tf32(v.z), f2tf32(v.w));
            *(uint4*)&As[row * ASTRIDE + 4 * c8] = u;
        }
#pragma unroll
        for (int i = 0; i < 4; i++) {
            int c = cb * 4 + i;   // 0..7
            float4 v = *(const float4*)(w + (size_t)(bn + nb) * F_IN + k0 + 4 * c);
            Bs[(4 * c + 0) * BSTRIDE + nb] = f2tf32(v.x);
            Bs[(4 * c + 1) * BSTRIDE + nb] = f2tf32(v.y);
            Bs[(4 * c + 2) * BSTRIDE + nb] = f2tf32(v.z);
            Bs[(4 * c + 3) * BSTRIDE + nb] = f2tf32(v.w);
        }
        __syncthreads();

#pragma unroll
        for (int ks = 0; ks < 4; ks++) {
            int kk = ks * 8;
            unsigned a[2][4], b[4][2];
#pragma unroll
            for (int mt = 0; mt < 2; mt++) {
                int ar = wm * 32 + mt * 16;
                a[mt][0] = As[(ar + gid) * ASTRIDE + kk + tig];
                a[mt][1] = As[(ar + gid + 8) * ASTRIDE + kk + tig];
                a[mt][2] = As[(ar + gid) * ASTRIDE + kk + tig + 4];
                a[mt][3] = As[(ar + gid + 8) * ASTRIDE + kk + tig + 4];
            }
#pragma unroll
            for (int nt = 0; nt < 4; nt++) {
                int nc = wn * 32 + nt * 8 + gid;
                b[nt][0] = Bs[(kk + tig) * BSTRIDE + nc];
                b[nt][1] = Bs[(kk + tig + 4) * BSTRIDE + nc];
            }
#pragma unroll
            for (int mt = 0; mt < 2; mt++)
#pragma unroll
                for (int nt = 0; nt < 4; nt++)
                    mma_tf32(acc[mt][nt], a[mt], b[nt]);
        }
        __syncthreads();
    }

#pragma unroll
    for (int mt = 0; mt < 2; mt++) {
        int mrow0 = bm + wm * 32 + mt * 16 + gid;
#pragma unroll
        for (int nt = 0; nt < 4; nt++) {
            int ncol = bn + wn * 32 + nt * 8 + 2 * tig;
            float b0 = bias[ncol], b1 = bias[ncol + 1];
            if (mrow0 < N_REAL) {
                float v0 = acc[mt][nt][0] + b0, v1 = acc[mt][nt][1] + b1;
                g_xh[mrow0 * H1 + ncol]     = v0 > 0.f ? v0 : 0.f;
                g_xh[mrow0 * H1 + ncol + 1] = v1 > 0.f ? v1 : 0.f;
            }
            if (mrow0 + 8 < N_REAL) {
                float v2 = acc[mt][nt][2] + b0, v3 = acc[mt][nt][3] + b1;
                g_xh[(mrow0 + 8) * H1 + ncol]     = v2 > 0.f ? v2 : 0.f;
                g_xh[(mrow0 + 8) * H1 + ncol + 1] = v3 > 0.f ? v3 : 0.f;
            }
        }
    }
}

// ---------------------------------------------------------------------------
// Slotted CSR build — NO scan, no cross-block sync.  Each node owns a fixed
// 256-slot range (max degree ~137 for Binomial(300K, 1/3000): overflow is
// 15-sigma impossible).  Per-block smem histogram -> one spread global
// atomic per distinct dst per block -> smem-cursor placement.
__global__ void __launch_bounds__(1024) csr_kernel(const int* __restrict__ ei, int E) {
    __shared__ int hcnt [3000];
    __shared__ int hbase[3000];
    const int tid = threadIdx.x;
    const int CH = (E + gridDim.x - 1) / gridDim.x;
    const int lo = blockIdx.x * CH;
    const int hi = min(E, lo + CH);

    for (int i = tid; i < 3000; i += blockDim.x) hcnt[i] = 0;
    __syncthreads();
    for (int e = lo + tid; e < hi; e += blockDim.x)
        atomicAdd(&hcnt[ei[E + e]], 1);
    __syncthreads();
    for (int i = tid; i < 3000; i += blockDim.x) {
        int c = hcnt[i];
        if (c) hbase[i] = (i << 8) + atomicAdd(&g_cur[i], c);
        hcnt[i] = 0;
    }
    __syncthreads();
    for (int e = lo + tid; e < hi; e += blockDim.x) {
        int d = ei[E + e];
        int p = atomicAdd(&hcnt[d], 1);
        g_csr[hbase[d] + p] = ei[e];
    }
}

// ---------------------------------------------------------------------------
// Gather: one 64-thread block per dst node; thread t owns float4 features
// [4t, 4t+4).  Row offsets pre-scaled into smem (kills per-load IMAD);
// 8-edge unroll -> 8 outstanding LDG.128 per thread.
__global__ void gather_kernel() {
    const int n = blockIdx.x;
    const int t = threadIdx.x;        // 0..63
    const int deg = g_cur[n];
    const int base = n << 8;

    __shared__ int soff[64];
    float4 acc = make_float4(0.f, 0.f, 0.f, 0.f);
    const float* __restrict__ xh = g_xh + 4 * t;

    for (int j0 = 0; j0 < deg; j0 += 64) {
        int m = min(64, deg - j0);
        if (t < m) soff[t] = g_csr[base + j0 + t] * H1;
        __syncthreads();
        int j = 0;
        for (; j + 8 <= m; j += 8) {
            const float4 a0 = *(const float4*)(xh + soff[j]);
            const float4 a1 = *(const float4*)(xh + soff[j + 1]);
            const float4 a2 = *(const float4*)(xh + soff[j + 2]);
            const float4 a3 = *(const float4*)(xh + soff[j + 3]);
            const float4 a4 = *(const float4*)(xh + soff[j + 4]);
            const float4 a5 = *(const float4*)(xh + soff[j + 5]);
            const float4 a6 = *(const float4*)(xh + soff[j + 6]);
            const float4 a7 = *(const float4*)(xh + soff[j + 7]);
            acc.x += ((a0.x + a1.x) + (a2.x + a3.x)) + ((a4.x + a5.x) + (a6.x + a7.x));
            acc.y += ((a0.y + a1.y) + (a2.y + a3.y)) + ((a4.y + a5.y) + (a6.y + a7.y));
            acc.z += ((a0.z + a1.z) + (a2.z + a3.z)) + ((a4.z + a5.z) + (a6.z + a7.z));
            acc.w += ((a0.w + a1.w) + (a2.w + a3.w)) + ((a4.w + a5.w) + (a6.w + a7.w));
        }
        for (; j < m; j++) {
            const float4 a = *(const float4*)(xh + soff[j]);
            acc.x += a.x; acc.y += a.y; acc.z += a.z; acc.w += a.w;
        }
        __syncthreads();
    }
    float inv = 1.f / fmaxf((float)deg, 1.f);
    acc.x *= inv; acc.y *= inv; acc.z *= inv; acc.w *= inv;
    *(float4*)(g_agg + n * H1 + 4 * t) = acc;
}

// ---------------------------------------------------------------------------
// GEMM2 (tf32): gate[m, j] = sum_k A[m,k]*B[k,j] + bx[j] + bh[j]
//   A[m,k] = (k<256) ? agg[m,k] : xh[m,k-256]   (M=3000, K=512)
//   B[k,j], j = gate*128+o: (k<256) ? Wx_rel[gate,k,o] : Wx_root[gate,k-256,o]
__global__ void gemm2_kernel(const float* __restrict__ Wrel,
                             const float* __restrict__ Wroot,
                             const float* __restrict__ bx,
                             const float* __restrict__ bh) {
    __shared__ unsigned As[64 * ASTRIDE];
    __shared__ unsigned Bs[32 * BSTRIDE];
    const int bm = blockIdx.y * 64;
    const int bn = blockIdx.x * 64;
    const int tid = threadIdx.x;
    const int warp = tid >> 5, lane = tid & 31;
    const int wm = warp >> 1, wn = warp & 1;
    const int gid = lane >> 2, tig = lane & 3;
    const int gate = bn >> 7;
    const int obase = bn & 127;

    float acc[2][4][4];
#pragma unroll
    for (int mt = 0; mt < 2; mt++)
#pragma unroll
        for (int nt = 0; nt < 4; nt++)
#pragma unroll
            for (int r = 0; r < 4; r++) acc[mt][nt][r] = 0.f;

    const int r0 = tid >> 3;
    const int c8 = tid & 7;
    const int ob = tid & 63;
    const int kc = tid >> 6;     // 0..1

    for (int k0 = 0; k0 < 2 * H1; k0 += 32) {
        const float* Abase = (k0 < H1) ? (g_agg + k0) : (g_xh + (k0 - H1));
#pragma unroll
        for (int rr = 0; rr < 4; rr++) {
            int row = r0 + rr * 16;
            int gm = bm + row;
            float4 v = make_float4(0.f, 0.f, 0.f, 0.f);
            if (gm < N_PAD)
                v = *(const float4*)(Abase + (size_t)gm * H1 + 4 * c8);
            uint4 u = make_uint4(f2tf32(v.x), f2tf32(v.y), f2tf32(v.z), f2tf32(v.w));
            *(uint4*)&As[row * ASTRIDE + 4 * c8] = u;
        }
        const float* Wbase = (k0 < H1)
            ? (Wrel  + (size_t)gate * H1 * OUTD + (size_t)k0 * OUTD + obase)
            : (Wroot + (size_t)gate * H1 * OUTD + (size_t)(k0 - H1) * OUTD + obase);
#pragma unroll
        for (int i = 0; i < 16; i++) {
            int k = kc * 16 + i;
            Bs[k * BSTRIDE + ob] = f2tf32(Wbase[(size_t)k * OUTD + ob]);
        }
        __syncthreads();

#pragma unroll
        for (int ks = 0; ks < 4; ks++) {
            int kk = ks * 8;
            unsigned a[2][4], b[4][2];
#pragma unroll
            for (int mt = 0; mt < 2; mt++) {
                int ar = wm * 32 + mt * 16;
                a[mt][0] = As[(ar + gid) * ASTRIDE + kk + tig];
                a[mt][1] = As[(ar + gid + 8) * ASTRIDE + kk + tig];
                a[mt][2] = As[(ar + gid) * ASTRIDE + kk + tig + 4];
                a[mt][3] = As[(ar + gid + 8) * ASTRIDE + kk + tig + 4];
            }
#pragma unroll
            for (int nt = 0; nt < 4; nt++) {
                int nc = wn * 32 + nt * 8 + gid;
                b[nt][0] = Bs[(kk + tig) * BSTRIDE + nc];
                b[nt][1] = Bs[(kk + tig + 4) * BSTRIDE + nc];
            }
#pragma unroll
            for (int mt = 0; mt < 2; mt++)
#pragma unroll
                for (int nt = 0; nt < 4; nt++)
                    mma_tf32(acc[mt][nt], a[mt], b[nt]);
        }
        __syncthreads();
    }

#pragma unroll
    for (int mt = 0; mt < 2; mt++) {
        int mrow0 = bm + wm * 32 + mt * 16 + gid;
#pragma unroll
        for (int nt = 0; nt < 4; nt++) {
            int ncol = bn + wn * 32 + nt * 8 + 2 * tig;      // global gate col
            float b0 = bx[ncol] + bh[ncol];
            float b1 = bx[ncol + 1] + bh[ncol + 1];
            if (mrow0 < N_PAD) {
                g_gate[(size_t)mrow0 * GATES_N + ncol]     = acc[mt][nt][0] + b0;
                g_gate[(size_t)mrow0 * GATES_N + ncol + 1] = acc[mt][nt][1] + b1;
            }
            if (mrow0 + 8 < N_PAD) {
                g_gate[(size_t)(mrow0 + 8) * GATES_N + ncol]     = acc[mt][nt][2] + b0;
                g_gate[(size_t)(mrow0 + 8) * GATES_N + ncol + 1] = acc[mt][nt][3] + b1;
            }
        }
    }
}

// ---------------------------------------------------------------------------
// Gates + H + final projection. C_prev = 0 so forget gate is dead.
__global__ void finish_kernel(const float* __restrict__ fcw,
                              const float* __restrict__ fcb,
                              float* __restrict__ out,
                              float* __restrict__ Hout) {
    int n = blockIdx.x;       // 0..2999
    int o = threadIdx.x;      // 0..127
    const float* g = g_gate + (size_t)n * GATES_N;
    float gi = g[o];
    float gc = g[2 * OUTD + o];
    float go = g[3 * OUTD + o];
    float I = 1.f / (1.f + __expf(-gi));
    float T = tanhf(gc);
    float O = 1.f / (1.f + __expf(-go));
    float C = I * T;
    float H = O * tanhf(C);
    Hout[n * OUTD + o] = H;

    float v = H * fcw[o];
#pragma unroll
    for (int s = 16; s > 0; s >>= 1)
        v += __shfl_down_sync(0xffffffffu, v, s);
    __shared__ float sred[4];
    if ((o & 31) == 0) sred[o >> 5] = v;
    __syncthreads();
    if (o == 0 && n < N_REAL)
        out[n] = sred[0] + sred[1] + sred[2] + sred[3] + fcb[0];
}

// ---------------------------------------------------------------------------
extern "C" void kernel_launch(void* const* d_in, const int* in_sizes, int n_in,
                              void* d_out, int out_size) {
    const float* x      = (const float*)d_in[0];
    const int*   ei     = (const int*)  d_in[1];
    const float* fc0_w  = (const float*)d_in[2];
    const float* fc0_b  = (const float*)d_in[3];
    const float* Wx_rel = (const float*)d_in[4];
    const float* Wx_root= (const float*)d_in[5];
    const float* bx     = (const float*)d_in[6];
    // d_in[7] Wh_rel, d_in[8] Wh_root: multiplied by zero state -> unused
    const float* bh     = (const float*)d_in[9];
    const float* fc_w   = (const float*)d_in[10];
    const float* fc_b   = (const float*)d_in[11];
    const int E = in_sizes[1] / 2;

    float* out  = (float*)d_out;          // [2500]
    float* Hout = out + N_REAL;           // [3000 x 128]

    init_kernel<<<((N_PAD - N_REAL) * H1 + 255) / 256, 256>>>(fc0_b);

    dim3 g1(H1 / 64, (N_REAL + 63) / 64);          // 4 x 40
    gemm1_kernel<<<g1, 128>>>(x, fc0_w, fc0_b);

    csr_kernel<<<CSR_BLOCKS, 1024>>>(ei, E);
    gather_kernel<<<N_PAD, 64>>>();

    dim3 g2(GATES_N / 64, (N_PAD + 63) / 64);      // 8 x 47
    gemm2_kernel<<<g2, 128>>>(Wx_rel, Wx_root, bx, bh);

    finish_kernel<<<N_PAD, OUTD>>>(fc_w, fc_b, out, Hout);
}